// round 2
// baseline (speedup 1.0000x reference)
#include <cuda_runtime.h>
#include <cstdint>

// ---------------------------------------------------------------------------
// GeoEEGSNN forward: B=64, C=64, T=1024, Tq=256
// Pipeline:
//   k_mapper : curv/tang 1x1 conv + pool4           -> g_curv,g_tang [Tq][B][32]
//   k_encode : pop-encode (4 gaussians) + spatialW  -> g_s [24][B*T]
//   k_bnstats: per-channel mean/var -> scale/shift  (24 ch)
//   k_conv   : BN2+ELU + depthwise15 + pointwise    -> g_pw [32][B*T]
//   k_bnstats: per-channel mean/var                 (32 ch)
//   k_scan   : BN1+ELU+pool4 fused + LIF scan + FC  -> out [64][4]
// ---------------------------------------------------------------------------

#define B 64
#define CDIM 64
#define T 1024
#define BT (B*T)           // 65536
#define TQ 256

__device__ float g_s [24 * BT];        // pre-BN spatial output, [ch][b*T+t]
__device__ float g_pw[32 * BT];        // pre-BN pointwise output, [ch][b*T+t]
__device__ float g_curv[TQ * B * 32];  // [tq][b][o]
__device__ float g_tang[TQ * B * 32];
__device__ float g_bn2_scale[24], g_bn2_shift[24];
__device__ float g_bn1_scale[32], g_bn1_shift[32];

__device__ __forceinline__ float eluf(float x) {
    return x > 0.0f ? x : expm1f(x);
}

// ---------------------------------------------------------------------------
// K1: geometric mappers. pool4 commutes with the 1x1 conv (both linear), so
// pool first (4x fewer FMAs). One thread per (b, tq).
// ---------------------------------------------------------------------------
__global__ void k_mapper(const float* __restrict__ xb,
                         const float* __restrict__ curvW,
                         const float* __restrict__ tangW) {
    __shared__ float wc[32 * 64];
    __shared__ float wt[32 * 64];
    for (int i = threadIdx.x; i < 2048; i += blockDim.x) {
        wc[i] = curvW[i];
        wt[i] = tangW[i];
    }
    __syncthreads();

    int id = blockIdx.x * blockDim.x + threadIdx.x;  // 16384 = 64 * 256
    int b  = id >> 8;
    int tq = id & 255;

    float a1[32], a2[32];
#pragma unroll
    for (int o = 0; o < 32; o++) { a1[o] = 0.0f; a2[o] = 0.0f; }

    const float* x1 = xb + ((size_t)(b * 3 + 1) * CDIM) * T + tq * 4;
    const float* x2 = xb + ((size_t)(b * 3 + 2) * CDIM) * T + tq * 4;

    for (int c = 0; c < CDIM; c++) {
        float4 v1 = *(const float4*)(x1 + (size_t)c * T);
        float4 v2 = *(const float4*)(x2 + (size_t)c * T);
        float p1 = (v1.x + v1.y + v1.z + v1.w) * 0.25f;
        float p2 = (v2.x + v2.y + v2.z + v2.w) * 0.25f;
#pragma unroll
        for (int o = 0; o < 32; o++) {
            a1[o] = fmaf(p1, wc[o * 64 + c], a1[o]);
            a2[o] = fmaf(p2, wt[o * 64 + c], a2[o]);
        }
    }

    int base = tq * (B * 32) + b * 32;
#pragma unroll
    for (int o = 0; o < 32; o++) {
        g_curv[base + o] = a1[o];
        g_tang[base + o] = a2[o];
    }
}

// ---------------------------------------------------------------------------
// K2: population encoding + grouped spatial conv. One thread per (b, t).
//   enc[b,f,c,t,p] = exp(-(x - mu[p])^2 / (2 sigma[p]^2 + 1e-6))
//   s[b, (f*4+p)*2+d, t] = sum_c enc * spatialW[f*4+p, d, c]
// Output stored channel-major for BN reduction + conv coalescing.
// ---------------------------------------------------------------------------
__global__ void k_encode(const float* __restrict__ xb,
                         const float* __restrict__ mu,
                         const float* __restrict__ sigma,
                         const float* __restrict__ spatialW) {
    __shared__ float2 sw[12][64];   // (d=0, d=1) weight pairs per (g, c)
    for (int i = threadIdx.x; i < 768; i += blockDim.x) {
        int g = i >> 6, c = i & 63;
        sw[g][c] = make_float2(spatialW[(g * 2 + 0) * 64 + c],
                               spatialW[(g * 2 + 1) * 64 + c]);
    }
    __syncthreads();

    float smu[4], sneg[4];
#pragma unroll
    for (int p = 0; p < 4; p++) {
        float sg = __ldg(sigma + p);
        smu[p]  = __ldg(mu + p);
        sneg[p] = -1.0f / (2.0f * sg * sg + 1e-6f);
    }

    int id = blockIdx.x * blockDim.x + threadIdx.x;  // 65536
    int b  = id >> 10;
    int t  = id & 1023;

    float acc[24];
#pragma unroll
    for (int i = 0; i < 24; i++) acc[i] = 0.0f;

#pragma unroll
    for (int f = 0; f < 3; f++) {
        const float* xp = xb + ((size_t)(b * 3 + f) * CDIM) * T + t;
        for (int c = 0; c < CDIM; c++) {
            float x = __ldg(xp + (size_t)c * T);
#pragma unroll
            for (int p = 0; p < 4; p++) {
                float d = x - smu[p];
                float e = expf(d * d * sneg[p]);
                float2 w = sw[f * 4 + p][c];
                acc[(f * 4 + p) * 2 + 0] = fmaf(e, w.x, acc[(f * 4 + p) * 2 + 0]);
                acc[(f * 4 + p) * 2 + 1] = fmaf(e, w.y, acc[(f * 4 + p) * 2 + 1]);
            }
        }
    }

#pragma unroll
    for (int ch = 0; ch < 24; ch++)
        g_s[(size_t)ch * BT + id] = acc[ch];
}

// ---------------------------------------------------------------------------
// K3/K5: training-mode BN statistics per channel over B*T elements.
// One block per channel. Emits fused scale = g*rsqrt(var+eps),
// shift = b - mean*scale.
// ---------------------------------------------------------------------------
__global__ void k_bnstats(const float* __restrict__ data,
                          const float* __restrict__ gamma,
                          const float* __restrict__ beta,
                          float* __restrict__ scale,
                          float* __restrict__ shift) {
    int ch = blockIdx.x;
    const float* p = data + (size_t)ch * BT;
    float s = 0.0f, s2 = 0.0f;
    for (int i = threadIdx.x; i < BT; i += blockDim.x) {
        float v = p[i];
        s  += v;
        s2 += v * v;
    }
    __shared__ float rs[256], rq[256];
    rs[threadIdx.x] = s;
    rq[threadIdx.x] = s2;
    __syncthreads();
    for (int st = 128; st > 0; st >>= 1) {
        if (threadIdx.x < st) {
            rs[threadIdx.x] += rs[threadIdx.x + st];
            rq[threadIdx.x] += rq[threadIdx.x + st];
        }
        __syncthreads();
    }
    if (threadIdx.x == 0) {
        float mean = rs[0] * (1.0f / BT);
        float var  = fmaxf(rq[0] * (1.0f / BT) - mean * mean, 0.0f);
        float sc   = gamma[ch] * rsqrtf(var + 1e-5f);
        scale[ch] = sc;
        shift[ch] = beta[ch] - mean * sc;
    }
}

// ---------------------------------------------------------------------------
// K4: BN2 + ELU + depthwise conv1d(k=15, pad=7) + pointwise (24->32).
// Block = (b, 256-wide t-tile). Shared tile holds post-activation values
// with halo (zero padding outside [0, T) applied post-activation, matching
// lax.conv zero-padding of the activated input).
// ---------------------------------------------------------------------------
__global__ void k_conv(const float* __restrict__ dwW,
                       const float* __restrict__ pwW) {
    __shared__ float sh[24][272];        // 270 used (256 + 14 halo)
    __shared__ float sdw[24][16];
    __shared__ float spw[32][24];

    int b  = blockIdx.x >> 2;
    int tt = blockIdx.x & 3;
    int t0 = tt * 256;
    int tid = threadIdx.x;

    for (int i = tid; i < 360; i += blockDim.x) sdw[i / 15][i % 15] = dwW[i];
    for (int i = tid; i < 768; i += blockDim.x) spw[i / 24][i % 24] = pwW[i];

    for (int i = tid; i < 24 * 270; i += blockDim.x) {
        int ch = i / 270, j = i % 270;
        int t = t0 + j - 7;
        float v = 0.0f;
        if (t >= 0 && t < T) {
            float raw = g_s[(size_t)ch * BT + b * T + t];
            float y = fmaf(raw, __ldg(&g_bn2_scale[ch]), __ldg(&g_bn2_shift[ch]));
            v = eluf(y);
        }
        sh[ch][j] = v;
    }
    __syncthreads();

    float dwv[24];
#pragma unroll
    for (int ch = 0; ch < 24; ch++) {
        float a = 0.0f;
#pragma unroll
        for (int k = 0; k < 15; k++)
            a = fmaf(sh[ch][tid + k], sdw[ch][k], a);
        dwv[ch] = a;
    }

    int t = t0 + tid;
#pragma unroll
    for (int o = 0; o < 32; o++) {
        float a = 0.0f;
#pragma unroll
        for (int ch = 0; ch < 24; ch++)
            a = fmaf(dwv[ch], spw[o][ch], a);
        g_pw[(size_t)o * BT + b * T + t] = a;
    }
}

// ---------------------------------------------------------------------------
// K6: fused BN1+ELU+pool4 + SmoothGDLIF scan + FC head.
// One block per batch element b (64 blocks x 32 threads). Lane = channel o.
// All operand arrays (g_pw 8MB, g_curv/g_tang 2MB each) are L2-resident.
// ---------------------------------------------------------------------------
__global__ void k_scan(const float* __restrict__ tau_geo,
                       const float* __restrict__ beta_m,
                       const float* __restrict__ alpha,
                       const float* __restrict__ gamma_p,
                       const float* __restrict__ fcW,
                       const float* __restrict__ fcb,
                       float* __restrict__ out) {
    int b = blockIdx.x;
    int o = threadIdx.x;      // 0..31

    float tau    = 1.0f / (1.0f + expf(-tau_geo[0]));
    float om_tau = 1.0f - tau;
    float beta   = beta_m[0];
    float al     = alpha[0];
    float gp     = gamma_p[0];
    float sc     = g_bn1_scale[o];
    float shf    = g_bn1_shift[o];

    const float* pwp = g_pw   + (size_t)o * BT + b * T;
    const float* cup = g_curv + b * 32 + o;
    const float* tap = g_tang + b * 32 + o;

    float m = 0.0f, cs = 0.0f, ts = 0.0f, fr = 0.0f;

    // software-pipelined loads
    float4 v   = *(const float4*)(pwp);
    float  cu  = cup[0];
    float  ta  = tap[0];

    for (int tq = 0; tq < TQ; tq++) {
        int nq = (tq + 1 < TQ) ? tq + 1 : TQ - 1;
        float4 vn  = *(const float4*)(pwp + (size_t)nq * 4);
        float  cun = cup[(size_t)nq * (B * 32)];
        float  tan_ = tap[(size_t)nq * (B * 32)];

        float y0 = eluf(fmaf(v.x, sc, shf));
        float y1 = eluf(fmaf(v.y, sc, shf));
        float y2 = eluf(fmaf(v.z, sc, shf));
        float y3 = eluf(fmaf(v.w, sc, shf));
        float x_t = (y0 + y1 + y2 + y3) * 0.25f;

        cs = tau * cs + om_tau * cu;
        ts = tau * ts + om_tau * ta;
        float vth  = fmaxf(0.3f + al * cs, 0.1f);
        float sens = 1.0f / (1.0f + expf(-(1.0f - gp * ts)));
        float mn   = beta * m + x_t * sens;
        float sp   = (mn - vth) > 0.0f ? 1.0f : 0.0f;
        m  = mn - sp * vth;
        fr += sp;

        v = vn; cu = cun; ta = tan_;
    }

    fr *= (1.0f / (float)TQ);

    // FC head: out[b,k] = sum_o fr[o] * fcW[k,o] + fcb[k]; warp reduce per k.
    float res[4];
#pragma unroll
    for (int k = 0; k < 4; k++) {
        float vv = fr * __ldg(fcW + k * 32 + o);
#pragma unroll
        for (int off = 16; off > 0; off >>= 1)
            vv += __shfl_xor_sync(0xffffffff, vv, off);
        res[k] = vv;
    }
    if (o == 0) {
#pragma unroll
        for (int k = 0; k < 4; k++)
            out[b * 4 + k] = res[k] + __ldg(fcb + k);
    }
}

// ---------------------------------------------------------------------------
// Launch. Inputs in metadata order:
//  0 xb, 1 mu, 2 sigma, 3 curvW, 4 tangW, 5 spatialW, 6 bn2_g, 7 bn2_b,
//  8 dwW, 9 pwW, 10 bn1_g, 11 bn1_b, 12 tau_geo, 13 beta_m, 14 alpha,
//  15 gamma_p, 16 fcW, 17 fcb
// ---------------------------------------------------------------------------
extern "C" void kernel_launch(void* const* d_in, const int* in_sizes, int n_in,
                              void* d_out, int out_size) {
    const float* xb       = (const float*)d_in[0];
    const float* mu       = (const float*)d_in[1];
    const float* sigma    = (const float*)d_in[2];
    const float* curvW    = (const float*)d_in[3];
    const float* tangW    = (const float*)d_in[4];
    const float* spatialW = (const float*)d_in[5];
    const float* bn2_g    = (const float*)d_in[6];
    const float* bn2_b    = (const float*)d_in[7];
    const float* dwW      = (const float*)d_in[8];
    const float* pwW      = (const float*)d_in[9];
    const float* bn1_g    = (const float*)d_in[10];
    const float* bn1_b    = (const float*)d_in[11];
    const float* tau_geo  = (const float*)d_in[12];
    const float* beta_m   = (const float*)d_in[13];
    const float* alpha    = (const float*)d_in[14];
    const float* gamma_p  = (const float*)d_in[15];
    const float* fcW      = (const float*)d_in[16];
    const float* fcb      = (const float*)d_in[17];
    float* out            = (float*)d_out;

    float* s_ptr;   cudaGetSymbolAddress((void**)&s_ptr,  g_s);
    float* pw_ptr;  cudaGetSymbolAddress((void**)&pw_ptr, g_pw);
    float* bn2sc;   cudaGetSymbolAddress((void**)&bn2sc,  g_bn2_scale);
    float* bn2sh;   cudaGetSymbolAddress((void**)&bn2sh,  g_bn2_shift);
    float* bn1sc;   cudaGetSymbolAddress((void**)&bn1sc,  g_bn1_scale);
    float* bn1sh;   cudaGetSymbolAddress((void**)&bn1sh,  g_bn1_shift);

    k_mapper<<<64, 256>>>(xb, curvW, tangW);
    k_encode<<<256, 256>>>(xb, mu, sigma, spatialW);
    k_bnstats<<<24, 256>>>(s_ptr, bn2_g, bn2_b, bn2sc, bn2sh);
    k_conv<<<256, 256>>>(dwW, pwW);
    k_bnstats<<<32, 256>>>(pw_ptr, bn1_g, bn1_b, bn1sc, bn1sh);
    k_scan<<<64, 32>>>(tau_geo, beta_m, alpha, gamma_p, fcW, fcb, out);
}

// round 3
// speedup vs baseline: 1.2461x; 1.2461x over previous
#include <cuda_runtime.h>
#include <cstdint>

// ---------------------------------------------------------------------------
// GeoEEGSNN forward: B=64, C=64, T=1024, Tq=256
//   k_mapper : curv/tang 1x1 conv + pool4 (commutes)    -> g_curv,g_tang [Tq][B][32]
//   k_encode : pop-encode + spatialW + BN2 partials     -> g_s [24][B*T]
//   k_bnfin  : deterministic partial-sum finalize       -> bn2 scale/shift
//   k_conv   : BN2+ELU + dw15 + pw + BN1 partials       -> g_pw [32][B*T]
//   k_bnfin  :                                          -> bn1 scale/shift
//   k_prelif : BN1+ELU+pool4, scan-friendly layout      -> g_x [Tq][B][32]
//   k_scan   : cs/ts/m recurrences + FC head            -> out [64][4]
// ---------------------------------------------------------------------------

#define B 64
#define CDIM 64
#define T 1024
#define BT (B*T)           // 65536
#define TQ 256
#define NCTA_ENC 256
#define NCTA_CONV 512

__device__ float g_s [24 * BT];        // pre-BN spatial output, [ch][b*T+t]
__device__ float g_pw[32 * BT];        // pre-BN pointwise output, [ch][b*T+t]
__device__ float g_curv[TQ * B * 32];  // [tq][b][o]
__device__ float g_tang[TQ * B * 32];
__device__ float g_x   [TQ * B * 32];  // pooled post-BN1-ELU input to LIF
__device__ float g_ep_sum[24 * NCTA_ENC],  g_ep_sq[24 * NCTA_ENC];
__device__ float g_cp_sum[32 * NCTA_CONV], g_cp_sq[32 * NCTA_CONV];
__device__ float g_bn2_scale[24], g_bn2_shift[24];
__device__ float g_bn1_scale[32], g_bn1_shift[32];

__device__ __forceinline__ float eluf(float x) {
    return x > 0.0f ? x : expm1f(x);
}

// ---------------------------------------------------------------------------
// K1: geometric mappers; pool4 first (linear), then 1x1 conv. Thread=(b,tq).
// ---------------------------------------------------------------------------
__global__ void k_mapper(const float* __restrict__ xb,
                         const float* __restrict__ curvW,
                         const float* __restrict__ tangW) {
    __shared__ float wc[32 * 64];
    __shared__ float wt[32 * 64];
    for (int i = threadIdx.x; i < 2048; i += blockDim.x) {
        wc[i] = curvW[i];
        wt[i] = tangW[i];
    }
    __syncthreads();

    int id = blockIdx.x * blockDim.x + threadIdx.x;  // 16384 = 64 * 256
    int b  = id >> 8;
    int tq = id & 255;

    float a1[32], a2[32];
#pragma unroll
    for (int o = 0; o < 32; o++) { a1[o] = 0.0f; a2[o] = 0.0f; }

    const float* x1 = xb + ((size_t)(b * 3 + 1) * CDIM) * T + tq * 4;
    const float* x2 = xb + ((size_t)(b * 3 + 2) * CDIM) * T + tq * 4;

    for (int c = 0; c < CDIM; c++) {
        float4 v1 = *(const float4*)(x1 + (size_t)c * T);
        float4 v2 = *(const float4*)(x2 + (size_t)c * T);
        float p1 = (v1.x + v1.y + v1.z + v1.w) * 0.25f;
        float p2 = (v2.x + v2.y + v2.z + v2.w) * 0.25f;
#pragma unroll
        for (int o = 0; o < 32; o++) {
            a1[o] = fmaf(p1, wc[o * 64 + c], a1[o]);
            a2[o] = fmaf(p2, wt[o * 64 + c], a2[o]);
        }
    }

    int base = tq * (B * 32) + b * 32;
#pragma unroll
    for (int o = 0; o < 32; o++) {
        g_curv[base + o] = a1[o];
        g_tang[base + o] = a2[o];
    }
}

// ---------------------------------------------------------------------------
// K2: population encoding + grouped spatial conv + BN2 block-partials.
// Thread = (b, t). 256 blocks x 256 threads.
// ---------------------------------------------------------------------------
__global__ void k_encode(const float* __restrict__ xb,
                         const float* __restrict__ mu,
                         const float* __restrict__ sigma,
                         const float* __restrict__ spatialW) {
    __shared__ float2 sw[12][64];
    __shared__ float red_s[8][24], red_q[8][24];
    for (int i = threadIdx.x; i < 768; i += blockDim.x) {
        int g = i >> 6, c = i & 63;
        sw[g][c] = make_float2(spatialW[(g * 2 + 0) * 64 + c],
                               spatialW[(g * 2 + 1) * 64 + c]);
    }
    __syncthreads();

    float smu[4], sneg[4];
#pragma unroll
    for (int p = 0; p < 4; p++) {
        float sg = __ldg(sigma + p);
        smu[p]  = __ldg(mu + p);
        sneg[p] = -1.0f / (2.0f * sg * sg + 1e-6f);
    }

    int id = blockIdx.x * blockDim.x + threadIdx.x;  // 65536
    int b  = id >> 10;
    int t  = id & 1023;

    float acc[24];
#pragma unroll
    for (int i = 0; i < 24; i++) acc[i] = 0.0f;

#pragma unroll
    for (int f = 0; f < 3; f++) {
        const float* xp = xb + ((size_t)(b * 3 + f) * CDIM) * T + t;
        for (int c = 0; c < CDIM; c++) {
            float x = __ldg(xp + (size_t)c * T);
#pragma unroll
            for (int p = 0; p < 4; p++) {
                float d = x - smu[p];
                float e = expf(d * d * sneg[p]);
                float2 w = sw[f * 4 + p][c];
                acc[(f * 4 + p) * 2 + 0] = fmaf(e, w.x, acc[(f * 4 + p) * 2 + 0]);
                acc[(f * 4 + p) * 2 + 1] = fmaf(e, w.y, acc[(f * 4 + p) * 2 + 1]);
            }
        }
    }

#pragma unroll
    for (int ch = 0; ch < 24; ch++)
        g_s[(size_t)ch * BT + id] = acc[ch];

    // BN2 block partials (deterministic: warp shuffle + fixed-order combine)
    int w = threadIdx.x >> 5, lane = threadIdx.x & 31;
#pragma unroll
    for (int ch = 0; ch < 24; ch++) {
        float s = acc[ch];
        float q = s * s;
#pragma unroll
        for (int off = 16; off > 0; off >>= 1) {
            s += __shfl_xor_sync(0xffffffffu, s, off);
            q += __shfl_xor_sync(0xffffffffu, q, off);
        }
        if (lane == 0) { red_s[w][ch] = s; red_q[w][ch] = q; }
    }
    __syncthreads();
    if (threadIdx.x < 24) {
        float S = 0.0f, Q = 0.0f;
#pragma unroll
        for (int ww = 0; ww < 8; ww++) { S += red_s[ww][threadIdx.x]; Q += red_q[ww][threadIdx.x]; }
        g_ep_sum[threadIdx.x * NCTA_ENC + blockIdx.x] = S;
        g_ep_sq [threadIdx.x * NCTA_ENC + blockIdx.x] = Q;
    }
}

// ---------------------------------------------------------------------------
// BN finalize: one block per channel, deterministic fixed-order reduction of
// per-CTA partials. scale = g*rsqrt(var+eps), shift = b - mean*scale.
// ---------------------------------------------------------------------------
__global__ void k_bnfin(const float* __restrict__ sump,
                        const float* __restrict__ sqp, int np,
                        const float* __restrict__ gamma,
                        const float* __restrict__ beta,
                        float* __restrict__ scale,
                        float* __restrict__ shift) {
    int ch = blockIdx.x;
    float s = 0.0f, q = 0.0f;
    for (int i = threadIdx.x; i < np; i += 256) {
        s += sump[ch * np + i];
        q += sqp [ch * np + i];
    }
    __shared__ float rs[8], rq[8];
    int w = threadIdx.x >> 5, lane = threadIdx.x & 31;
#pragma unroll
    for (int off = 16; off > 0; off >>= 1) {
        s += __shfl_xor_sync(0xffffffffu, s, off);
        q += __shfl_xor_sync(0xffffffffu, q, off);
    }
    if (lane == 0) { rs[w] = s; rq[w] = q; }
    __syncthreads();
    if (threadIdx.x == 0) {
        float S = 0.0f, Q = 0.0f;
#pragma unroll
        for (int ww = 0; ww < 8; ww++) { S += rs[ww]; Q += rq[ww]; }
        float mean = S * (1.0f / BT);
        float var  = fmaxf(Q * (1.0f / BT) - mean * mean, 0.0f);
        float sc   = gamma[ch] * rsqrtf(var + 1e-5f);
        scale[ch]  = sc;
        shift[ch]  = beta[ch] - mean * sc;
    }
}

// ---------------------------------------------------------------------------
// K4: BN2+ELU + depthwise(15, pad 7) + pointwise(24->32) + BN1 partials.
// 128-thread blocks, 128-wide t-tiles: 512 CTAs for better wave balance.
// ---------------------------------------------------------------------------
__global__ void __launch_bounds__(128, 6)
k_conv(const float* __restrict__ dwW,
       const float* __restrict__ pwW) {
    __shared__ float sh[24][144];        // 142 used (128 + 14 halo)
    __shared__ float sdw[24][16];
    __shared__ float spw[32][24];
    __shared__ float red_s[4][32], red_q[4][32];

    int b  = blockIdx.x >> 3;
    int tt = blockIdx.x & 7;
    int t0 = tt * 128;
    int tid = threadIdx.x;

    for (int i = tid; i < 360; i += 128) sdw[i / 15][i % 15] = dwW[i];
    for (int i = tid; i < 768; i += 128) spw[i / 24][i % 24] = pwW[i];

    for (int i = tid; i < 24 * 142; i += 128) {
        int ch = i / 142, j = i % 142;
        int t = t0 + j - 7;
        float v = 0.0f;
        if (t >= 0 && t < T) {
            float raw = g_s[(size_t)ch * BT + b * T + t];
            float y = fmaf(raw, g_bn2_scale[ch], g_bn2_shift[ch]);
            v = eluf(y);
        }
        sh[ch][j] = v;
    }
    __syncthreads();

    float dwv[24];
#pragma unroll
    for (int ch = 0; ch < 24; ch++) {
        float a = 0.0f;
#pragma unroll
        for (int k = 0; k < 15; k++)
            a = fmaf(sh[ch][tid + k], sdw[ch][k], a);
        dwv[ch] = a;
    }

    int w = tid >> 5, lane = tid & 31;
    int t = t0 + tid;
#pragma unroll
    for (int o = 0; o < 32; o++) {
        float a = 0.0f;
#pragma unroll
        for (int ch = 0; ch < 24; ch++)
            a = fmaf(dwv[ch], spw[o][ch], a);
        g_pw[(size_t)o * BT + b * T + t] = a;

        float s = a, q = a * a;
#pragma unroll
        for (int off = 16; off > 0; off >>= 1) {
            s += __shfl_xor_sync(0xffffffffu, s, off);
            q += __shfl_xor_sync(0xffffffffu, q, off);
        }
        if (lane == 0) { red_s[w][o] = s; red_q[w][o] = q; }
    }
    __syncthreads();
    if (tid < 32) {
        float S = 0.0f, Q = 0.0f;
#pragma unroll
        for (int ww = 0; ww < 4; ww++) { S += red_s[ww][tid]; Q += red_q[ww][tid]; }
        g_cp_sum[tid * NCTA_CONV + blockIdx.x] = S;
        g_cp_sq [tid * NCTA_CONV + blockIdx.x] = Q;
    }
}

// ---------------------------------------------------------------------------
// K5: BN1 + ELU + pool4 into scan-friendly layout [tq][b][o].
// Block = (b, 8 tq) x 256 threads (tid = tq_sub*32 + o). Grid 2048.
// ---------------------------------------------------------------------------
__global__ void k_prelif() {
    int b   = blockIdx.x >> 5;
    int tq  = (blockIdx.x & 31) * 8 + (threadIdx.x >> 5);
    int o   = threadIdx.x & 31;

    float4 v = *(const float4*)(g_pw + (size_t)o * BT + b * T + tq * 4);
    float sc = g_bn1_scale[o], shf = g_bn1_shift[o];
    float y0 = eluf(fmaf(v.x, sc, shf));
    float y1 = eluf(fmaf(v.y, sc, shf));
    float y2 = eluf(fmaf(v.z, sc, shf));
    float y3 = eluf(fmaf(v.w, sc, shf));
    g_x[tq * (B * 32) + b * 32 + o] = (y0 + y1 + y2 + y3) * 0.25f;
}

// ---------------------------------------------------------------------------
// K6: SmoothGDLIF recurrences (cs, ts, m) + FC head. One block per b,
// lane = channel. All per-step loads are coalesced 128B from L2-resident
// [tq][b][o] arrays; serial chain is fma/cmp/sel only (~36 instr/iter).
// ---------------------------------------------------------------------------
__global__ void k_scan(const float* __restrict__ tau_geo,
                       const float* __restrict__ beta_m,
                       const float* __restrict__ alpha,
                       const float* __restrict__ gamma_p,
                       const float* __restrict__ fcW,
                       const float* __restrict__ fcb,
                       float* __restrict__ out) {
    int b = blockIdx.x;
    int o = threadIdx.x;

    float tau    = 1.0f / (1.0f + expf(-tau_geo[0]));
    float om_tau = 1.0f - tau;
    float beta   = beta_m[0];
    float al     = alpha[0];
    float gp     = gamma_p[0];

    const float* xp  = g_x    + b * 32 + o;
    const float* cup = g_curv + b * 32 + o;
    const float* tap = g_tang + b * 32 + o;

    float m = 0.0f, cs = 0.0f, ts = 0.0f, fr = 0.0f;

    float xv = xp[0], cu = cup[0], ta = tap[0];

    for (int tq = 0; tq < TQ; tq++) {
        int nq = (tq + 1 < TQ) ? tq + 1 : TQ - 1;
        float xn  = xp [(size_t)nq * (B * 32)];
        float cun = cup[(size_t)nq * (B * 32)];
        float tan_= tap[(size_t)nq * (B * 32)];

        cs = fmaf(tau, cs, om_tau * cu);
        ts = fmaf(tau, ts, om_tau * ta);
        float vth  = fmaxf(fmaf(al, cs, 0.3f), 0.1f);
        float a    = fmaf(-gp, ts, 1.0f);
        float sens = 1.0f / (1.0f + expf(-a));
        float mn   = fmaf(beta, m, xv * sens);
        float sp   = (mn - vth) > 0.0f ? 1.0f : 0.0f;
        m  = fmaf(-sp, vth, mn);
        fr += sp;

        xv = xn; cu = cun; ta = tan_;
    }

    fr *= (1.0f / (float)TQ);

    float res[4];
#pragma unroll
    for (int k = 0; k < 4; k++) {
        float vv = fr * __ldg(fcW + k * 32 + o);
#pragma unroll
        for (int off = 16; off > 0; off >>= 1)
            vv += __shfl_xor_sync(0xffffffffu, vv, off);
        res[k] = vv;
    }
    if (o == 0) {
#pragma unroll
        for (int k = 0; k < 4; k++)
            out[b * 4 + k] = res[k] + __ldg(fcb + k);
    }
}

// ---------------------------------------------------------------------------
extern "C" void kernel_launch(void* const* d_in, const int* in_sizes, int n_in,
                              void* d_out, int out_size) {
    const float* xb       = (const float*)d_in[0];
    const float* mu       = (const float*)d_in[1];
    const float* sigma    = (const float*)d_in[2];
    const float* curvW    = (const float*)d_in[3];
    const float* tangW    = (const float*)d_in[4];
    const float* spatialW = (const float*)d_in[5];
    const float* bn2_g    = (const float*)d_in[6];
    const float* bn2_b    = (const float*)d_in[7];
    const float* dwW      = (const float*)d_in[8];
    const float* pwW      = (const float*)d_in[9];
    const float* bn1_g    = (const float*)d_in[10];
    const float* bn1_b    = (const float*)d_in[11];
    const float* tau_geo  = (const float*)d_in[12];
    const float* beta_m   = (const float*)d_in[13];
    const float* alpha    = (const float*)d_in[14];
    const float* gamma_p  = (const float*)d_in[15];
    const float* fcW      = (const float*)d_in[16];
    const float* fcb      = (const float*)d_in[17];
    float* out            = (float*)d_out;

    float* ep_s;  cudaGetSymbolAddress((void**)&ep_s,  g_ep_sum);
    float* ep_q;  cudaGetSymbolAddress((void**)&ep_q,  g_ep_sq);
    float* cp_s;  cudaGetSymbolAddress((void**)&cp_s,  g_cp_sum);
    float* cp_q;  cudaGetSymbolAddress((void**)&cp_q,  g_cp_sq);
    float* bn2sc; cudaGetSymbolAddress((void**)&bn2sc, g_bn2_scale);
    float* bn2sh; cudaGetSymbolAddress((void**)&bn2sh, g_bn2_shift);
    float* bn1sc; cudaGetSymbolAddress((void**)&bn1sc, g_bn1_scale);
    float* bn1sh; cudaGetSymbolAddress((void**)&bn1sh, g_bn1_shift);

    k_mapper<<<128, 128>>>(xb, curvW, tangW);
    k_encode<<<NCTA_ENC, 256>>>(xb, mu, sigma, spatialW);
    k_bnfin<<<24, 256>>>(ep_s, ep_q, NCTA_ENC, bn2_g, bn2_b, bn2sc, bn2sh);
    k_conv<<<NCTA_CONV, 128>>>(dwW, pwW);
    k_bnfin<<<32, 256>>>(cp_s, cp_q, NCTA_CONV, bn1_g, bn1_b, bn1sc, bn1sh);
    k_prelif<<<2048, 256>>>();
    k_scan<<<64, 32>>>(tau_geo, beta_m, alpha, gamma_p, fcW, fcb, out);
}

// round 4
// speedup vs baseline: 2.4919x; 1.9997x over previous
#include <cuda_runtime.h>
#include <cstdint>

// ---------------------------------------------------------------------------
// GeoEEGSNN forward: B=64, C=64, T=1024, Tq=256
//   k_mapper : curv/tang 1x1 conv + pool4 (commutes)    -> g_curv,g_tang [b][tq][o]
//   k_encode : pop-encode (ratio trick) + spatialW + BN2 partials -> g_s [ch][b*T+t]
//   k_bnfin  : deterministic partial finalize           -> bn2 scale/shift
//   k_conv   : BN2+ELU + dw15 + pw + BN1 partials       -> g_pw [o][b*T+t]
//   k_bnfin  :                                          -> bn1 scale/shift
//   k_prelif : BN1+ELU+pool4                            -> g_x [b][tq][o]
//   k_scan   : LIF recurrences (8-deep prefetch) + FC   -> out [64][4]
// ---------------------------------------------------------------------------

#define B 64
#define CDIM 64
#define T 1024
#define BT (B*T)           // 65536
#define TQ 256
#define NCTA_ENC 256
#define NCTA_CONV 512

__device__ float g_s [24 * BT];
__device__ float g_pw[32 * BT];
__device__ float g_curv[B * TQ * 32];   // [b][tq][o]
__device__ float g_tang[B * TQ * 32];
__device__ float g_x   [B * TQ * 32];
__device__ float g_ep_sum[24 * NCTA_ENC],  g_ep_sq[24 * NCTA_ENC];
__device__ float g_cp_sum[32 * NCTA_CONV], g_cp_sq[32 * NCTA_CONV];
__device__ float g_bn2_scale[24], g_bn2_shift[24];
__device__ float g_bn1_scale[32], g_bn1_shift[32];

__device__ __forceinline__ float eluf(float x) {
    return x > 0.0f ? x : expm1f(x);
}

// ---------------------------------------------------------------------------
// K1: mappers. pool4 first (linear). 256 blocks x 128 thr.
// thread = (tq in 64-tile, half) computing 16 o's for both features.
// ---------------------------------------------------------------------------
__global__ void __launch_bounds__(128)
k_mapper(const float* __restrict__ xb,
         const float* __restrict__ curvW,
         const float* __restrict__ tangW) {
    __shared__ float wcT[64][32];   // [c][o]
    __shared__ float wtT[64][32];
    for (int i = threadIdx.x; i < 2048; i += 128) {
        int o = i >> 6, c = i & 63;
        wcT[c][o] = curvW[i];
        wtT[c][o] = tangW[i];
    }
    __syncthreads();

    int b   = blockIdx.x >> 2;
    int tq  = (blockIdx.x & 3) * 64 + (threadIdx.x & 63);
    int ob  = (threadIdx.x >> 6) * 16;

    float a1[16], a2[16];
#pragma unroll
    for (int j = 0; j < 16; j++) { a1[j] = 0.0f; a2[j] = 0.0f; }

    const float* x1 = xb + ((size_t)(b * 3 + 1) * CDIM) * T + tq * 4;
    const float* x2 = xb + ((size_t)(b * 3 + 2) * CDIM) * T + tq * 4;

#pragma unroll 4
    for (int c = 0; c < CDIM; c++) {
        float4 v1 = *(const float4*)(x1 + (size_t)c * T);
        float4 v2 = *(const float4*)(x2 + (size_t)c * T);
        float p1 = (v1.x + v1.y + v1.z + v1.w) * 0.25f;
        float p2 = (v2.x + v2.y + v2.z + v2.w) * 0.25f;
#pragma unroll
        for (int j4 = 0; j4 < 4; j4++) {
            float4 w1 = *(const float4*)&wcT[c][ob + j4 * 4];
            float4 w2 = *(const float4*)&wtT[c][ob + j4 * 4];
            a1[j4*4+0] = fmaf(p1, w1.x, a1[j4*4+0]);
            a1[j4*4+1] = fmaf(p1, w1.y, a1[j4*4+1]);
            a1[j4*4+2] = fmaf(p1, w1.z, a1[j4*4+2]);
            a1[j4*4+3] = fmaf(p1, w1.w, a1[j4*4+3]);
            a2[j4*4+0] = fmaf(p2, w2.x, a2[j4*4+0]);
            a2[j4*4+1] = fmaf(p2, w2.y, a2[j4*4+1]);
            a2[j4*4+2] = fmaf(p2, w2.z, a2[j4*4+2]);
            a2[j4*4+3] = fmaf(p2, w2.w, a2[j4*4+3]);
        }
    }

    size_t base = (size_t)b * (TQ * 32) + (size_t)tq * 32 + ob;
#pragma unroll
    for (int j4 = 0; j4 < 4; j4++) {
        *(float4*)(g_curv + base + j4 * 4) =
            make_float4(a1[j4*4+0], a1[j4*4+1], a1[j4*4+2], a1[j4*4+3]);
        *(float4*)(g_tang + base + j4 * 4) =
            make_float4(a2[j4*4+0], a2[j4*4+1], a2[j4*4+2], a2[j4*4+3]);
    }
}

// ---------------------------------------------------------------------------
// K2: population encoding + grouped spatial conv + BN2 partials.
// Ratio trick when mu uniformly spaced & sigma shared: per sample
//   e_p = E0 * R^p * C_p,  E0=exp(q dx^2), R=exp(-2 q d dx), C_p=exp(q p^2 d^2)
// ---------------------------------------------------------------------------
__global__ void __launch_bounds__(256)
k_encode(const float* __restrict__ xb,
         const float* __restrict__ mu,
         const float* __restrict__ sigma,
         const float* __restrict__ spatialW) {
    __shared__ float2 sw[12][64];
    __shared__ float red_s[8][24], red_q[8][24];
    for (int i = threadIdx.x; i < 768; i += 256) {
        int g = i >> 6, c = i & 63;
        sw[g][c] = make_float2(spatialW[(g * 2 + 0) * 64 + c],
                               spatialW[(g * 2 + 1) * 64 + c]);
    }
    __syncthreads();

    float smu[4], sg[4];
#pragma unroll
    for (int p = 0; p < 4; p++) { smu[p] = __ldg(mu + p); sg[p] = __ldg(sigma + p); }

    float d = smu[1] - smu[0];
    bool uni = (fabsf((smu[2] - smu[1]) - d) <= 1e-5f * fmaxf(1.0f, fabsf(d))) &&
               (fabsf((smu[3] - smu[2]) - d) <= 1e-5f * fmaxf(1.0f, fabsf(d))) &&
               (fabsf(sg[1] - sg[0]) <= 1e-6f) &&
               (fabsf(sg[2] - sg[0]) <= 1e-6f) &&
               (fabsf(sg[3] - sg[0]) <= 1e-6f);

    int id = blockIdx.x * 256 + threadIdx.x;
    int b  = id >> 10;
    int t  = id & 1023;

    float acc[24];
#pragma unroll
    for (int i = 0; i < 24; i++) acc[i] = 0.0f;

    const float* xp0 = xb + ((size_t)(b * 3 + 0) * CDIM) * T + t;
    const float* xp1 = xb + ((size_t)(b * 3 + 1) * CDIM) * T + t;
    const float* xp2 = xb + ((size_t)(b * 3 + 2) * CDIM) * T + t;

    if (uni) {
        float q   = -1.0f / (2.0f * sg[0] * sg[0] + 1e-6f);
        float m0  = smu[0];
        float c1  = expf(q * d * d);
        float c2  = expf(q * 4.0f * d * d);
        float c3  = expf(q * 9.0f * d * d);
        float n2qd = -2.0f * q * d;
#pragma unroll 2
        for (int c = 0; c < CDIM; c++) {
            float xs[3];
            xs[0] = __ldg(xp0 + (size_t)c * T);
            xs[1] = __ldg(xp1 + (size_t)c * T);
            xs[2] = __ldg(xp2 + (size_t)c * T);
#pragma unroll
            for (int f = 0; f < 3; f++) {
                float dx = xs[f] - m0;
                float e0 = expf(q * dx * dx);
                float r  = expf(n2qd * dx);
                float r2 = r * r;
                float e1 = e0 * r * c1;
                float e2 = e0 * r2 * c2;
                float e3 = e0 * r2 * r * c3;
                float ee[4] = {e0, e1, e2, e3};
#pragma unroll
                for (int p = 0; p < 4; p++) {
                    float2 w = sw[f * 4 + p][c];
                    acc[(f*4+p)*2+0] = fmaf(ee[p], w.x, acc[(f*4+p)*2+0]);
                    acc[(f*4+p)*2+1] = fmaf(ee[p], w.y, acc[(f*4+p)*2+1]);
                }
            }
        }
    } else {
        float sneg[4];
#pragma unroll
        for (int p = 0; p < 4; p++) sneg[p] = -1.0f / (2.0f * sg[p] * sg[p] + 1e-6f);
#pragma unroll 2
        for (int c = 0; c < CDIM; c++) {
            float xs[3];
            xs[0] = __ldg(xp0 + (size_t)c * T);
            xs[1] = __ldg(xp1 + (size_t)c * T);
            xs[2] = __ldg(xp2 + (size_t)c * T);
#pragma unroll
            for (int f = 0; f < 3; f++) {
#pragma unroll
                for (int p = 0; p < 4; p++) {
                    float dx = xs[f] - smu[p];
                    float e  = expf(dx * dx * sneg[p]);
                    float2 w = sw[f * 4 + p][c];
                    acc[(f*4+p)*2+0] = fmaf(e, w.x, acc[(f*4+p)*2+0]);
                    acc[(f*4+p)*2+1] = fmaf(e, w.y, acc[(f*4+p)*2+1]);
                }
            }
        }
    }

#pragma unroll
    for (int ch = 0; ch < 24; ch++)
        g_s[(size_t)ch * BT + id] = acc[ch];

    int w = threadIdx.x >> 5, lane = threadIdx.x & 31;
#pragma unroll
    for (int ch = 0; ch < 24; ch++) {
        float s = acc[ch];
        float qv = s * s;
#pragma unroll
        for (int off = 16; off > 0; off >>= 1) {
            s  += __shfl_xor_sync(0xffffffffu, s, off);
            qv += __shfl_xor_sync(0xffffffffu, qv, off);
        }
        if (lane == 0) { red_s[w][ch] = s; red_q[w][ch] = qv; }
    }
    __syncthreads();
    if (threadIdx.x < 24) {
        float S = 0.0f, Q = 0.0f;
#pragma unroll
        for (int ww = 0; ww < 8; ww++) { S += red_s[ww][threadIdx.x]; Q += red_q[ww][threadIdx.x]; }
        g_ep_sum[threadIdx.x * NCTA_ENC + blockIdx.x] = S;
        g_ep_sq [threadIdx.x * NCTA_ENC + blockIdx.x] = Q;
    }
}

// ---------------------------------------------------------------------------
// BN finalize (deterministic fixed-order).
// ---------------------------------------------------------------------------
__global__ void k_bnfin(const float* __restrict__ sump,
                        const float* __restrict__ sqp, int np,
                        const float* __restrict__ gamma,
                        const float* __restrict__ beta,
                        float* __restrict__ scale,
                        float* __restrict__ shift) {
    int ch = blockIdx.x;
    float s = 0.0f, q = 0.0f;
    for (int i = threadIdx.x; i < np; i += 256) {
        s += sump[ch * np + i];
        q += sqp [ch * np + i];
    }
    __shared__ float rs[8], rq[8];
    int w = threadIdx.x >> 5, lane = threadIdx.x & 31;
#pragma unroll
    for (int off = 16; off > 0; off >>= 1) {
        s += __shfl_xor_sync(0xffffffffu, s, off);
        q += __shfl_xor_sync(0xffffffffu, q, off);
    }
    if (lane == 0) { rs[w] = s; rq[w] = q; }
    __syncthreads();
    if (threadIdx.x == 0) {
        float S = 0.0f, Q = 0.0f;
#pragma unroll
        for (int ww = 0; ww < 8; ww++) { S += rs[ww]; Q += rq[ww]; }
        float mean = S * (1.0f / BT);
        float var  = fmaxf(Q * (1.0f / BT) - mean * mean, 0.0f);
        float sc   = gamma[ch] * rsqrtf(var + 1e-5f);
        scale[ch]  = sc;
        shift[ch]  = beta[ch] - mean * sc;
    }
}

// ---------------------------------------------------------------------------
// K4: BN2+ELU + dw15 + pw(24->32) + BN1 partials.
// 512 blocks x 256 threads; t-tile = 128. dw split over 2 ch-halves,
// pw split over 2 o-halves with register-cached dwv + float4 weight LDS.
// ---------------------------------------------------------------------------
__global__ void __launch_bounds__(256)
k_conv(const float* __restrict__ dwW,
       const float* __restrict__ pwW) {
    __shared__ float sh[24][144];        // 142 used
    __shared__ float sdw[24][16];
    __shared__ float spw[32][24];
    __shared__ float dwv[24][132];       // 128 used
    __shared__ float red_s[8][16], red_q[8][16];

    int b   = blockIdx.x >> 3;
    int t0  = (blockIdx.x & 7) * 128;
    int tid = threadIdx.x;

    for (int i = tid; i < 360; i += 256) sdw[i / 15][i % 15] = dwW[i];
    for (int i = tid; i < 768; i += 256) spw[i / 24][i % 24] = pwW[i];

    for (int i = tid; i < 24 * 142; i += 256) {
        int ch = i / 142, j = i % 142;
        int t = t0 + j - 7;
        float v = 0.0f;
        if (t >= 0 && t < T) {
            float raw = g_s[(size_t)ch * BT + b * T + t];
            v = eluf(fmaf(raw, g_bn2_scale[ch], g_bn2_shift[ch]));
        }
        sh[ch][j] = v;
    }
    __syncthreads();

    int tl = tid & 127;
    int g  = tid >> 7;      // 0/1

    // depthwise: each half does 12 channels
#pragma unroll
    for (int cc = 0; cc < 12; cc++) {
        int ch = g * 12 + cc;
        float a = 0.0f;
#pragma unroll
        for (int k = 0; k < 15; k++)
            a = fmaf(sh[ch][tl + k], sdw[ch][k], a);
        dwv[ch][tl] = a;
    }
    __syncthreads();

    // pointwise: each half does 16 outputs for its t
    float dreg[24];
#pragma unroll
    for (int ch = 0; ch < 24; ch++) dreg[ch] = dwv[ch][tl];

    int wid = tid >> 5, lane = tid & 31;
    int t = t0 + tl;
#pragma unroll
    for (int oo = 0; oo < 16; oo++) {
        int o = g * 16 + oo;
        float a = 0.0f;
#pragma unroll
        for (int c4 = 0; c4 < 6; c4++) {
            float4 w = *(const float4*)&spw[o][c4 * 4];
            a = fmaf(dreg[c4*4+0], w.x, a);
            a = fmaf(dreg[c4*4+1], w.y, a);
            a = fmaf(dreg[c4*4+2], w.z, a);
            a = fmaf(dreg[c4*4+3], w.w, a);
        }
        g_pw[(size_t)o * BT + b * T + t] = a;

        float s = a, q = a * a;
#pragma unroll
        for (int off = 16; off > 0; off >>= 1) {
            s += __shfl_xor_sync(0xffffffffu, s, off);
            q += __shfl_xor_sync(0xffffffffu, q, off);
        }
        if (lane == 0) { red_s[wid][oo] = s; red_q[wid][oo] = q; }
    }
    __syncthreads();
    if (tid < 32) {
        int o = tid;
        int oo = o & 15;
        int w0 = (o >> 4) * 4;
        float S = 0.0f, Q = 0.0f;
#pragma unroll
        for (int ww = 0; ww < 4; ww++) { S += red_s[w0 + ww][oo]; Q += red_q[w0 + ww][oo]; }
        g_cp_sum[o * NCTA_CONV + blockIdx.x] = S;
        g_cp_sq [o * NCTA_CONV + blockIdx.x] = Q;
    }
}

// ---------------------------------------------------------------------------
// K5: BN1 + ELU + pool4 -> g_x [b][tq][o].
// ---------------------------------------------------------------------------
__global__ void __launch_bounds__(256)
k_prelif() {
    int b  = blockIdx.x >> 5;
    int tq = (blockIdx.x & 31) * 8 + (threadIdx.x >> 5);
    int o  = threadIdx.x & 31;

    float4 v = *(const float4*)(g_pw + (size_t)o * BT + b * T + tq * 4);
    float sc = g_bn1_scale[o], shf = g_bn1_shift[o];
    float y0 = eluf(fmaf(v.x, sc, shf));
    float y1 = eluf(fmaf(v.y, sc, shf));
    float y2 = eluf(fmaf(v.z, sc, shf));
    float y3 = eluf(fmaf(v.w, sc, shf));
    g_x[(size_t)b * (TQ * 32) + tq * 32 + o] = (y0 + y1 + y2 + y3) * 0.25f;
}

// ---------------------------------------------------------------------------
// K6: LIF recurrences + FC. 64 blocks x 32 thr. 8-deep register prefetch
// ring hides L2 latency (24 loads in flight).
// ---------------------------------------------------------------------------
__global__ void __launch_bounds__(32)
k_scan(const float* __restrict__ tau_geo,
       const float* __restrict__ beta_m,
       const float* __restrict__ alpha,
       const float* __restrict__ gamma_p,
       const float* __restrict__ fcW,
       const float* __restrict__ fcb,
       float* __restrict__ out) {
    int b = blockIdx.x;
    int o = threadIdx.x;

    float tau    = 1.0f / (1.0f + expf(-tau_geo[0]));
    float om_tau = 1.0f - tau;
    float beta   = beta_m[0];
    float al     = alpha[0];
    float gp     = gamma_p[0];

    const float* xp  = g_x    + (size_t)b * (TQ * 32) + o;
    const float* cup = g_curv + (size_t)b * (TQ * 32) + o;
    const float* tap = g_tang + (size_t)b * (TQ * 32) + o;

    float px[8], pcu[8], pta[8];
#pragma unroll
    for (int i = 0; i < 8; i++) {
        px [i] = xp [i * 32];
        pcu[i] = cup[i * 32];
        pta[i] = tap[i * 32];
    }

    float m = 0.0f, cs = 0.0f, ts = 0.0f, fr = 0.0f;

#pragma unroll 8
    for (int tq = 0; tq < TQ; tq++) {
        int s = tq & 7;
        float xv = px[s], cu = pcu[s], ta = pta[s];
        int nl = tq + 8; if (nl > TQ - 1) nl = TQ - 1;
        px [s] = xp [nl * 32];
        pcu[s] = cup[nl * 32];
        pta[s] = tap[nl * 32];

        cs = fmaf(tau, cs, om_tau * cu);
        ts = fmaf(tau, ts, om_tau * ta);
        float vth  = fmaxf(fmaf(al, cs, 0.3f), 0.1f);
        float a    = fmaf(-gp, ts, 1.0f);
        float sens = 1.0f / (1.0f + expf(-a));
        float mn   = fmaf(beta, m, xv * sens);
        float sp   = (mn - vth) > 0.0f ? 1.0f : 0.0f;
        m  = fmaf(-sp, vth, mn);
        fr += sp;
    }

    fr *= (1.0f / (float)TQ);

    float res[4];
#pragma unroll
    for (int k = 0; k < 4; k++) {
        float vv = fr * __ldg(fcW + k * 32 + o);
#pragma unroll
        for (int off = 16; off > 0; off >>= 1)
            vv += __shfl_xor_sync(0xffffffffu, vv, off);
        res[k] = vv;
    }
    if (o == 0) {
#pragma unroll
        for (int k = 0; k < 4; k++)
            out[b * 4 + k] = res[k] + __ldg(fcb + k);
    }
}

// ---------------------------------------------------------------------------
extern "C" void kernel_launch(void* const* d_in, const int* in_sizes, int n_in,
                              void* d_out, int out_size) {
    const float* xb       = (const float*)d_in[0];
    const float* mu       = (const float*)d_in[1];
    const float* sigma    = (const float*)d_in[2];
    const float* curvW    = (const float*)d_in[3];
    const float* tangW    = (const float*)d_in[4];
    const float* spatialW = (const float*)d_in[5];
    const float* bn2_g    = (const float*)d_in[6];
    const float* bn2_b    = (const float*)d_in[7];
    const float* dwW      = (const float*)d_in[8];
    const float* pwW      = (const float*)d_in[9];
    const float* bn1_g    = (const float*)d_in[10];
    const float* bn1_b    = (const float*)d_in[11];
    const float* tau_geo  = (const float*)d_in[12];
    const float* beta_m   = (const float*)d_in[13];
    const float* alpha    = (const float*)d_in[14];
    const float* gamma_p  = (const float*)d_in[15];
    const float* fcW      = (const float*)d_in[16];
    const float* fcb      = (const float*)d_in[17];
    float* out            = (float*)d_out;

    float* ep_s;  cudaGetSymbolAddress((void**)&ep_s,  g_ep_sum);
    float* ep_q;  cudaGetSymbolAddress((void**)&ep_q,  g_ep_sq);
    float* cp_s;  cudaGetSymbolAddress((void**)&cp_s,  g_cp_sum);
    float* cp_q;  cudaGetSymbolAddress((void**)&cp_q,  g_cp_sq);
    float* bn2sc; cudaGetSymbolAddress((void**)&bn2sc, g_bn2_scale);
    float* bn2sh; cudaGetSymbolAddress((void**)&bn2sh, g_bn2_shift);
    float* bn1sc; cudaGetSymbolAddress((void**)&bn1sc, g_bn1_scale);
    float* bn1sh; cudaGetSymbolAddress((void**)&bn1sh, g_bn1_shift);

    k_mapper<<<256, 128>>>(xb, curvW, tangW);
    k_encode<<<NCTA_ENC, 256>>>(xb, mu, sigma, spatialW);
    k_bnfin<<<24, 256>>>(ep_s, ep_q, NCTA_ENC, bn2_g, bn2_b, bn2sc, bn2sh);
    k_conv<<<NCTA_CONV, 256>>>(dwW, pwW);
    k_bnfin<<<32, 256>>>(cp_s, cp_q, NCTA_CONV, bn1_g, bn1_b, bn1sc, bn1sh);
    k_prelif<<<2048, 256>>>();
    k_scan<<<64, 32>>>(tau_geo, beta_m, alpha, gamma_p, fcW, fcb, out);
}

// round 5
// speedup vs baseline: 2.6277x; 1.0545x over previous
#include <cuda_runtime.h>
#include <cstdint>

// ---------------------------------------------------------------------------
// GeoEEGSNN forward: B=64, C=64, T=1024, Tq=256
//   k_mapper : curv/tang 1x1 conv + pool4 (commutes)    -> g_curv,g_tang [b][tq][o]
//   k_encode : pop-encode (ratio trick, f-split) + BN2 partials -> g_s [ch][b*T+t]
//   k_bnfin  : deterministic partial finalize           -> bn2 scale/shift
//   k_conv   : BN2+ELU + dw15 + pw + BN1 partials       -> g_pw [o][b*T+t]
//   k_bnfin  :                                          -> bn1 scale/shift
//   k_prelif : BN1+ELU+pool4                            -> g_x [b][tq][o]
//   k_scan   : LIF recurrences (8-deep prefetch) + FC   -> out [64][4]
// ---------------------------------------------------------------------------

#define B 64
#define CDIM 64
#define T 1024
#define BT (B*T)           // 65536
#define TQ 256
#define NCTA_ENC 256       // blocks per feature
#define NCTA_CONV 1024

__device__ float g_s [24 * BT];
__device__ float g_pw[32 * BT];
__device__ float g_curv[B * TQ * 32];   // [b][tq][o]
__device__ float g_tang[B * TQ * 32];
__device__ float g_x   [B * TQ * 32];
__device__ float g_ep_sum[24 * NCTA_ENC],  g_ep_sq[24 * NCTA_ENC];
__device__ float g_cp_sum[32 * NCTA_CONV], g_cp_sq[32 * NCTA_CONV];
__device__ float g_bn2_scale[24], g_bn2_shift[24];
__device__ float g_bn1_scale[32], g_bn1_shift[32];

// ELU: negative branch via __expf(x)-1. abs err ~4e-7 (feeds averages only).
__device__ __forceinline__ float eluf(float x) {
    return x > 0.0f ? x : (__expf(x) - 1.0f);
}

// ---------------------------------------------------------------------------
// K1: mappers. pool4 first (linear). grid 256 x 256 thr.
// thread = (tq in 64-tile, feat(2), o-half(2)): 16 outputs for one feature.
// ---------------------------------------------------------------------------
__global__ void __launch_bounds__(256)
k_mapper(const float* __restrict__ xb,
         const float* __restrict__ curvW,
         const float* __restrict__ tangW) {
    __shared__ float wT[2][64][32];   // [feat][c][o]
    for (int i = threadIdx.x; i < 2048; i += 256) {
        int o = i >> 6, c = i & 63;
        wT[0][c][o] = curvW[i];
        wT[1][c][o] = tangW[i];
    }
    __syncthreads();

    int b    = blockIdx.x >> 2;
    int tq   = (blockIdx.x & 3) * 64 + (threadIdx.x & 63);
    int sub  = threadIdx.x >> 6;       // 0..3
    int feat = sub >> 1;               // 0=curv(ft1), 1=tang(ft2)
    int ob   = (sub & 1) * 16;

    float a[16];
#pragma unroll
    for (int j = 0; j < 16; j++) a[j] = 0.0f;

    const float* x = xb + ((size_t)(b * 3 + 1 + feat) * CDIM) * T + tq * 4;

#pragma unroll 4
    for (int c = 0; c < CDIM; c++) {
        float4 v = *(const float4*)(x + (size_t)c * T);
        float p = (v.x + v.y + v.z + v.w) * 0.25f;
#pragma unroll
        for (int j4 = 0; j4 < 4; j4++) {
            float4 w = *(const float4*)&wT[feat][c][ob + j4 * 4];
            a[j4*4+0] = fmaf(p, w.x, a[j4*4+0]);
            a[j4*4+1] = fmaf(p, w.y, a[j4*4+1]);
            a[j4*4+2] = fmaf(p, w.z, a[j4*4+2]);
            a[j4*4+3] = fmaf(p, w.w, a[j4*4+3]);
        }
    }

    float* dst = (feat == 0 ? g_curv : g_tang) +
                 (size_t)b * (TQ * 32) + (size_t)tq * 32 + ob;
#pragma unroll
    for (int j4 = 0; j4 < 4; j4++)
        *(float4*)(dst + j4 * 4) =
            make_float4(a[j4*4+0], a[j4*4+1], a[j4*4+2], a[j4*4+3]);
}

// ---------------------------------------------------------------------------
// K2: population encoding + grouped spatial conv + BN2 partials.
// 3-way feature split: grid 768, block 256, each block does one feature's
// 8 output channels. Ratio trick (uniform mu, shared sigma):
//   e_p = e0 * r^p * c_p ; c_p folded into LDS weights.
// ---------------------------------------------------------------------------
__global__ void __launch_bounds__(256)
k_encode(const float* __restrict__ xb,
         const float* __restrict__ mu,
         const float* __restrict__ sigma,
         const float* __restrict__ spatialW) {
    int f   = blockIdx.x >> 8;      // 0..2
    int blk = blockIdx.x & 255;

    float smu[4], sg[4];
#pragma unroll
    for (int p = 0; p < 4; p++) { smu[p] = __ldg(mu + p); sg[p] = __ldg(sigma + p); }
    float d = smu[1] - smu[0];
    bool uni = (fabsf((smu[2] - smu[1]) - d) <= 1e-5f * fmaxf(1.0f, fabsf(d))) &&
               (fabsf((smu[3] - smu[2]) - d) <= 1e-5f * fmaxf(1.0f, fabsf(d))) &&
               (fabsf(sg[1] - sg[0]) <= 1e-6f) &&
               (fabsf(sg[2] - sg[0]) <= 1e-6f) &&
               (fabsf(sg[3] - sg[0]) <= 1e-6f);
    float q    = -1.0f / (2.0f * sg[0] * sg[0] + 1e-6f);
    float m0   = smu[0];
    float n2qd = -2.0f * q * d;

    __shared__ float2 sw[4][64];     // weights for groups f*4+p, c_p folded (uni)
    __shared__ float red_s[8][8], red_q[8][8];
    {
        int i = threadIdx.x;         // 256 entries = 4 groups x 64 c
        int p = i >> 6, c = i & 63;
        int g = f * 4 + p;
        float cp = uni ? expf(q * (float)(p * p) * d * d) : 1.0f;
        sw[p][c] = make_float2(spatialW[(g * 2 + 0) * 64 + c] * cp,
                               spatialW[(g * 2 + 1) * 64 + c] * cp);
    }
    __syncthreads();

    int id = blk * 256 + threadIdx.x;
    int b  = id >> 10;
    int t  = id & 1023;

    float acc[8];
#pragma unroll
    for (int i = 0; i < 8; i++) acc[i] = 0.0f;

    const float* xp = xb + ((size_t)(b * 3 + f) * CDIM) * T + t;

    if (uni) {
#pragma unroll 4
        for (int c = 0; c < CDIM; c++) {
            float x  = __ldg(xp + (size_t)c * T);
            float dx = x - m0;
            float e0 = expf(q * dx * dx);
            float r  = expf(n2qd * dx);
            float e1 = e0 * r;
            float e2 = e1 * r;
            float e3 = e2 * r;
            float ee[4] = {e0, e1, e2, e3};
#pragma unroll
            for (int p = 0; p < 4; p++) {
                float2 w = sw[p][c];
                acc[p*2+0] = fmaf(ee[p], w.x, acc[p*2+0]);
                acc[p*2+1] = fmaf(ee[p], w.y, acc[p*2+1]);
            }
        }
    } else {
        float sneg[4];
#pragma unroll
        for (int p = 0; p < 4; p++) sneg[p] = -1.0f / (2.0f * sg[p] * sg[p] + 1e-6f);
#pragma unroll 2
        for (int c = 0; c < CDIM; c++) {
            float x = __ldg(xp + (size_t)c * T);
#pragma unroll
            for (int p = 0; p < 4; p++) {
                float dx = x - smu[p];
                float e  = expf(dx * dx * sneg[p]);
                float2 w = sw[p][c];
                acc[p*2+0] = fmaf(e, w.x, acc[p*2+0]);
                acc[p*2+1] = fmaf(e, w.y, acc[p*2+1]);
            }
        }
    }

#pragma unroll
    for (int cc = 0; cc < 8; cc++)
        g_s[(size_t)(f * 8 + cc) * BT + id] = acc[cc];

    int w = threadIdx.x >> 5, lane = threadIdx.x & 31;
#pragma unroll
    for (int cc = 0; cc < 8; cc++) {
        float s = acc[cc];
        float qv = s * s;
#pragma unroll
        for (int off = 16; off > 0; off >>= 1) {
            s  += __shfl_xor_sync(0xffffffffu, s, off);
            qv += __shfl_xor_sync(0xffffffffu, qv, off);
        }
        if (lane == 0) { red_s[w][cc] = s; red_q[w][cc] = qv; }
    }
    __syncthreads();
    if (threadIdx.x < 8) {
        float S = 0.0f, Q = 0.0f;
#pragma unroll
        for (int ww = 0; ww < 8; ww++) { S += red_s[ww][threadIdx.x]; Q += red_q[ww][threadIdx.x]; }
        g_ep_sum[(f * 8 + threadIdx.x) * NCTA_ENC + blk] = S;
        g_ep_sq [(f * 8 + threadIdx.x) * NCTA_ENC + blk] = Q;
    }
}

// ---------------------------------------------------------------------------
// BN finalize (deterministic fixed-order).
// ---------------------------------------------------------------------------
__global__ void k_bnfin(const float* __restrict__ sump,
                        const float* __restrict__ sqp, int np,
                        const float* __restrict__ gamma,
                        const float* __restrict__ beta,
                        float* __restrict__ scale,
                        float* __restrict__ shift) {
    int ch = blockIdx.x;
    float s = 0.0f, q = 0.0f;
    for (int i = threadIdx.x; i < np; i += 256) {
        s += sump[ch * np + i];
        q += sqp [ch * np + i];
    }
    __shared__ float rs[8], rq[8];
    int w = threadIdx.x >> 5, lane = threadIdx.x & 31;
#pragma unroll
    for (int off = 16; off > 0; off >>= 1) {
        s += __shfl_xor_sync(0xffffffffu, s, off);
        q += __shfl_xor_sync(0xffffffffu, q, off);
    }
    if (lane == 0) { rs[w] = s; rq[w] = q; }
    __syncthreads();
    if (threadIdx.x == 0) {
        float S = 0.0f, Q = 0.0f;
#pragma unroll
        for (int ww = 0; ww < 8; ww++) { S += rs[ww]; Q += rq[ww]; }
        float mean = S * (1.0f / BT);
        float var  = fmaxf(Q * (1.0f / BT) - mean * mean, 0.0f);
        float sc   = gamma[ch] * rsqrtf(var + 1e-5f);
        scale[ch]  = sc;
        shift[ch]  = beta[ch] - mean * sc;
    }
}

// ---------------------------------------------------------------------------
// K4: BN2+ELU + dw15 + pw(24->32) + BN1 partials.
// grid 1024 (64-t tiles), 256 thr. dw: 32 t-pairs x 8 ch-groups(3 ch),
// float2 LDS (9 loads per ch per t-pair). pw: 64 t x 4 o-groups(8 o).
// ---------------------------------------------------------------------------
__global__ void __launch_bounds__(256)
k_conv(const float* __restrict__ dwW,
       const float* __restrict__ pwW) {
    __shared__ float sh[24][80];         // 78 used (64 + 14 halo)
    __shared__ float sdw[24][16];
    __shared__ float spw[32][24];
    __shared__ float dwv[24][68];        // 64 used
    __shared__ float red_s[8][8], red_q[8][8];

    int b   = blockIdx.x >> 4;
    int t0  = (blockIdx.x & 15) * 64;
    int tid = threadIdx.x;

    for (int i = tid; i < 360; i += 256) sdw[i / 15][i % 15] = dwW[i];
    for (int i = tid; i < 768; i += 256) spw[i / 24][i % 24] = pwW[i];

    for (int i = tid; i < 24 * 78; i += 256) {
        int ch = i / 78, j = i % 78;
        int t = t0 + j - 7;
        float v = 0.0f;
        if (t >= 0 && t < T) {
            float raw = g_s[(size_t)ch * BT + b * T + t];
            v = eluf(fmaf(raw, g_bn2_scale[ch], g_bn2_shift[ch]));
        }
        sh[ch][j] = v;
    }
    __syncthreads();

    // depthwise: thread = (t-pair tp, ch-group cg of 3)
    {
        int tp = tid & 31;
        int cg = tid >> 5;
#pragma unroll
        for (int cc = 0; cc < 3; cc++) {
            int ch = cg * 3 + cc;
            float s[18];
#pragma unroll
            for (int j = 0; j < 9; j++) {
                float2 v = *(const float2*)&sh[ch][2 * tp + 2 * j];
                s[2*j] = v.x; s[2*j+1] = v.y;
            }
            float a0 = 0.0f, a1 = 0.0f;
#pragma unroll
            for (int k = 0; k < 15; k++) {
                float w = sdw[ch][k];
                a0 = fmaf(s[k],     w, a0);
                a1 = fmaf(s[k + 1], w, a1);
            }
            *(float2*)&dwv[ch][2 * tp] = make_float2(a0, a1);
        }
    }
    __syncthreads();

    // pointwise: thread = (t, o-group of 8)
    int tl = tid & 63;
    int og = tid >> 6;
    float dreg[24];
#pragma unroll
    for (int ch = 0; ch < 24; ch++) dreg[ch] = dwv[ch][tl];

    int wid = tid >> 5, lane = tid & 31;
    int t = t0 + tl;
#pragma unroll
    for (int oo = 0; oo < 8; oo++) {
        int o = og * 8 + oo;
        float a = 0.0f;
#pragma unroll
        for (int c4 = 0; c4 < 6; c4++) {
            float4 w = *(const float4*)&spw[o][c4 * 4];
            a = fmaf(dreg[c4*4+0], w.x, a);
            a = fmaf(dreg[c4*4+1], w.y, a);
            a = fmaf(dreg[c4*4+2], w.z, a);
            a = fmaf(dreg[c4*4+3], w.w, a);
        }
        g_pw[(size_t)o * BT + b * T + t] = a;

        float s = a, q = a * a;
#pragma unroll
        for (int off = 16; off > 0; off >>= 1) {
            s += __shfl_xor_sync(0xffffffffu, s, off);
            q += __shfl_xor_sync(0xffffffffu, q, off);
        }
        if (lane == 0) { red_s[wid][oo] = s; red_q[wid][oo] = q; }
    }
    __syncthreads();
    // 32 o's: o = og*8+oo covered by warps {og*2, og*2+1}
    if (tid < 32) {
        int o  = tid;
        int oo = o & 7;
        int w0 = (o >> 3) * 2;
        float S = red_s[w0][oo] + red_s[w0 + 1][oo];
        float Q = red_q[w0][oo] + red_q[w0 + 1][oo];
        g_cp_sum[o * NCTA_CONV + blockIdx.x] = S;
        g_cp_sq [o * NCTA_CONV + blockIdx.x] = Q;
    }
}

// ---------------------------------------------------------------------------
// K5: BN1 + ELU + pool4 -> g_x [b][tq][o].
// ---------------------------------------------------------------------------
__global__ void __launch_bounds__(256)
k_prelif() {
    int b  = blockIdx.x >> 5;
    int tq = (blockIdx.x & 31) * 8 + (threadIdx.x >> 5);
    int o  = threadIdx.x & 31;

    float4 v = *(const float4*)(g_pw + (size_t)o * BT + b * T + tq * 4);
    float sc = g_bn1_scale[o], shf = g_bn1_shift[o];
    float y0 = eluf(fmaf(v.x, sc, shf));
    float y1 = eluf(fmaf(v.y, sc, shf));
    float y2 = eluf(fmaf(v.z, sc, shf));
    float y3 = eluf(fmaf(v.w, sc, shf));
    g_x[(size_t)b * (TQ * 32) + tq * 32 + o] = (y0 + y1 + y2 + y3) * 0.25f;
}

// ---------------------------------------------------------------------------
// K6: LIF recurrences + FC. 64 blocks x 32 thr. 8-deep register prefetch.
// ---------------------------------------------------------------------------
__global__ void __launch_bounds__(32)
k_scan(const float* __restrict__ tau_geo,
       const float* __restrict__ beta_m,
       const float* __restrict__ alpha,
       const float* __restrict__ gamma_p,
       const float* __restrict__ fcW,
       const float* __restrict__ fcb,
       float* __restrict__ out) {
    int b = blockIdx.x;
    int o = threadIdx.x;

    float tau    = 1.0f / (1.0f + expf(-tau_geo[0]));
    float om_tau = 1.0f - tau;
    float beta   = beta_m[0];
    float al     = alpha[0];
    float gp     = gamma_p[0];

    const float* xp  = g_x    + (size_t)b * (TQ * 32) + o;
    const float* cup = g_curv + (size_t)b * (TQ * 32) + o;
    const float* tap = g_tang + (size_t)b * (TQ * 32) + o;

    float px[8], pcu[8], pta[8];
#pragma unroll
    for (int i = 0; i < 8; i++) {
        px [i] = xp [i * 32];
        pcu[i] = cup[i * 32];
        pta[i] = tap[i * 32];
    }

    float m = 0.0f, cs = 0.0f, ts = 0.0f, fr = 0.0f;

#pragma unroll 8
    for (int tq = 0; tq < TQ; tq++) {
        int s = tq & 7;
        float xv = px[s], cu = pcu[s], ta = pta[s];
        int nl = tq + 8; if (nl > TQ - 1) nl = TQ - 1;
        px [s] = xp [nl * 32];
        pcu[s] = cup[nl * 32];
        pta[s] = tap[nl * 32];

        cs = fmaf(tau, cs, om_tau * cu);
        ts = fmaf(tau, ts, om_tau * ta);
        float vth  = fmaxf(fmaf(al, cs, 0.3f), 0.1f);
        float a    = fmaf(-gp, ts, 1.0f);
        float sens = 1.0f / (1.0f + expf(-a));
        float mn   = fmaf(beta, m, xv * sens);
        float sp   = (mn - vth) > 0.0f ? 1.0f : 0.0f;
        m  = fmaf(-sp, vth, mn);
        fr += sp;
    }

    fr *= (1.0f / (float)TQ);

    float res[4];
#pragma unroll
    for (int k = 0; k < 4; k++) {
        float vv = fr * __ldg(fcW + k * 32 + o);
#pragma unroll
        for (int off = 16; off > 0; off >>= 1)
            vv += __shfl_xor_sync(0xffffffffu, vv, off);
        res[k] = vv;
    }
    if (o == 0) {
#pragma unroll
        for (int k = 0; k < 4; k++)
            out[b * 4 + k] = res[k] + __ldg(fcb + k);
    }
}

// ---------------------------------------------------------------------------
extern "C" void kernel_launch(void* const* d_in, const int* in_sizes, int n_in,
                              void* d_out, int out_size) {
    const float* xb       = (const float*)d_in[0];
    const float* mu       = (const float*)d_in[1];
    const float* sigma    = (const float*)d_in[2];
    const float* curvW    = (const float*)d_in[3];
    const float* tangW    = (const float*)d_in[4];
    const float* spatialW = (const float*)d_in[5];
    const float* bn2_g    = (const float*)d_in[6];
    const float* bn2_b    = (const float*)d_in[7];
    const float* dwW      = (const float*)d_in[8];
    const float* pwW      = (const float*)d_in[9];
    const float* bn1_g    = (const float*)d_in[10];
    const float* bn1_b    = (const float*)d_in[11];
    const float* tau_geo  = (const float*)d_in[12];
    const float* beta_m   = (const float*)d_in[13];
    const float* alpha    = (const float*)d_in[14];
    const float* gamma_p  = (const float*)d_in[15];
    const float* fcW      = (const float*)d_in[16];
    const float* fcb      = (const float*)d_in[17];
    float* out            = (float*)d_out;

    float* ep_s;  cudaGetSymbolAddress((void**)&ep_s,  g_ep_sum);
    float* ep_q;  cudaGetSymbolAddress((void**)&ep_q,  g_ep_sq);
    float* cp_s;  cudaGetSymbolAddress((void**)&cp_s,  g_cp_sum);
    float* cp_q;  cudaGetSymbolAddress((void**)&cp_q,  g_cp_sq);
    float* bn2sc; cudaGetSymbolAddress((void**)&bn2sc, g_bn2_scale);
    float* bn2sh; cudaGetSymbolAddress((void**)&bn2sh, g_bn2_shift);
    float* bn1sc; cudaGetSymbolAddress((void**)&bn1sc, g_bn1_scale);
    float* bn1sh; cudaGetSymbolAddress((void**)&bn1sh, g_bn1_shift);

    k_mapper<<<256, 256>>>(xb, curvW, tangW);
    k_encode<<<768, 256>>>(xb, mu, sigma, spatialW);
    k_bnfin<<<24, 256>>>(ep_s, ep_q, NCTA_ENC, bn2_g, bn2_b, bn2sc, bn2sh);
    k_conv<<<NCTA_CONV, 256>>>(dwW, pwW);
    k_bnfin<<<32, 256>>>(cp_s, cp_q, NCTA_CONV, bn1_g, bn1_b, bn1sc, bn1sh);
    k_prelif<<<2048, 256>>>();
    k_scan<<<64, 32>>>(tau_geo, beta_m, alpha, gamma_p, fcW, fcb, out);
}

// round 6
// speedup vs baseline: 2.9793x; 1.1338x over previous
#include <cuda_runtime.h>
#include <cstdint>

// ---------------------------------------------------------------------------
// GeoEEGSNN forward: B=64, C=64, T=1024, Tq=256. 5 launches:
//   k_front  : [0..767] encode (ratio trick, __expf) + BN2 partials
//              [768..1023] curv/tang mapper (pool4 first)
//   k_bnfin  : bn2 scale/shift finalize
//   k_conv   : BN2+ELU + dw15 + pw(24->32)          -> g_pw [o][b*T+t]
//   k_pwstats: vectorized BN1 partials (32ch x 16 seg)
//   k_scan   : bn1 finalize + BN1+ELU+pool4 (smem) + LIF scan + FC
// ---------------------------------------------------------------------------

#define B 64
#define CDIM 64
#define T 1024
#define BT (B*T)           // 65536
#define TQ 256
#define NCTA_ENC 256       // partial blocks per feature

__device__ float g_s [24 * BT];
__device__ float g_pw[32 * BT];
__device__ float g_curv[B * TQ * 32];   // [b][tq][o]
__device__ float g_tang[B * TQ * 32];
__device__ float g_ep_sum[24 * NCTA_ENC], g_ep_sq[24 * NCTA_ENC];
__device__ float g_cp_sum[32 * 16],       g_cp_sq[32 * 16];
__device__ float g_bn2_scale[24], g_bn2_shift[24];

__device__ __forceinline__ float eluf(float x) {
    return x > 0.0f ? x : (__expf(x) - 1.0f);
}

// ---------------------------------------------------------------------------
// K_front: fat kernel. Blocks [0,768): encode; [768,1024): mapper.
// Shared aliased via one buffer (mapper needs 16KB, encode 2.6KB).
// ---------------------------------------------------------------------------
__global__ void __launch_bounds__(256)
k_front(const float* __restrict__ xb,
        const float* __restrict__ curvW,
        const float* __restrict__ tangW,
        const float* __restrict__ mu,
        const float* __restrict__ sigma,
        const float* __restrict__ spatialW) {
    __shared__ __align__(16) char smem[16896];

    if (blockIdx.x < 768) {
        // ---------------- encode ----------------
        float2 (*sw)[64]   = (float2(*)[64])smem;            // 4*64*8 = 2048
        float  (*red_s)[8] = (float(*)[8])(smem + 2048);     // 256
        float  (*red_q)[8] = (float(*)[8])(smem + 2304);     // 256

        int f   = blockIdx.x >> 8;
        int blk = blockIdx.x & 255;

        float smu[4], sg[4];
#pragma unroll
        for (int p = 0; p < 4; p++) { smu[p] = __ldg(mu + p); sg[p] = __ldg(sigma + p); }
        float d = smu[1] - smu[0];
        bool uni = (fabsf((smu[2] - smu[1]) - d) <= 1e-5f * fmaxf(1.0f, fabsf(d))) &&
                   (fabsf((smu[3] - smu[2]) - d) <= 1e-5f * fmaxf(1.0f, fabsf(d))) &&
                   (fabsf(sg[1] - sg[0]) <= 1e-6f) &&
                   (fabsf(sg[2] - sg[0]) <= 1e-6f) &&
                   (fabsf(sg[3] - sg[0]) <= 1e-6f);
        float q    = -1.0f / (2.0f * sg[0] * sg[0] + 1e-6f);
        float m0   = smu[0];
        float n2qd = -2.0f * q * d;

        {
            int i = threadIdx.x;
            int p = i >> 6, c = i & 63;
            int g = f * 4 + p;
            float cp = uni ? expf(q * (float)(p * p) * d * d) : 1.0f;
            sw[p][c] = make_float2(spatialW[(g * 2 + 0) * 64 + c] * cp,
                                   spatialW[(g * 2 + 1) * 64 + c] * cp);
        }
        __syncthreads();

        int id = blk * 256 + threadIdx.x;
        int b  = id >> 10;
        int t  = id & 1023;

        float acc[8];
#pragma unroll
        for (int i = 0; i < 8; i++) acc[i] = 0.0f;

        const float* xp = xb + ((size_t)(b * 3 + f) * CDIM) * T + t;

        if (uni) {
#pragma unroll 4
            for (int c = 0; c < CDIM; c++) {
                float x  = __ldg(xp + (size_t)c * T);
                float dx = x - m0;
                float e0 = __expf(q * dx * dx);
                float r  = __expf(n2qd * dx);
                float e1 = e0 * r;
                float e2 = e1 * r;
                float e3 = e2 * r;
                float ee[4] = {e0, e1, e2, e3};
#pragma unroll
                for (int p = 0; p < 4; p++) {
                    float2 w = sw[p][c];
                    acc[p*2+0] = fmaf(ee[p], w.x, acc[p*2+0]);
                    acc[p*2+1] = fmaf(ee[p], w.y, acc[p*2+1]);
                }
            }
        } else {
            float sneg[4];
#pragma unroll
            for (int p = 0; p < 4; p++) sneg[p] = -1.0f / (2.0f * sg[p] * sg[p] + 1e-6f);
#pragma unroll 2
            for (int c = 0; c < CDIM; c++) {
                float x = __ldg(xp + (size_t)c * T);
#pragma unroll
                for (int p = 0; p < 4; p++) {
                    float dx = x - smu[p];
                    float e  = expf(dx * dx * sneg[p]);
                    float2 w = sw[p][c];
                    acc[p*2+0] = fmaf(e, w.x, acc[p*2+0]);
                    acc[p*2+1] = fmaf(e, w.y, acc[p*2+1]);
                }
            }
        }

#pragma unroll
        for (int cc = 0; cc < 8; cc++)
            g_s[(size_t)(f * 8 + cc) * BT + id] = acc[cc];

        int w = threadIdx.x >> 5, lane = threadIdx.x & 31;
#pragma unroll
        for (int cc = 0; cc < 8; cc++) {
            float s = acc[cc];
            float qv = s * s;
#pragma unroll
            for (int off = 16; off > 0; off >>= 1) {
                s  += __shfl_xor_sync(0xffffffffu, s, off);
                qv += __shfl_xor_sync(0xffffffffu, qv, off);
            }
            if (lane == 0) { red_s[w][cc] = s; red_q[w][cc] = qv; }
        }
        __syncthreads();
        if (threadIdx.x < 8) {
            float S = 0.0f, Q = 0.0f;
#pragma unroll
            for (int ww = 0; ww < 8; ww++) { S += red_s[ww][threadIdx.x]; Q += red_q[ww][threadIdx.x]; }
            g_ep_sum[(f * 8 + threadIdx.x) * NCTA_ENC + blk] = S;
            g_ep_sq [(f * 8 + threadIdx.x) * NCTA_ENC + blk] = Q;
        }
    } else {
        // ---------------- mapper ----------------
        float (*wT)[64][32] = (float(*)[64][32])smem;   // [feat][c][o], 16KB

        int mbid = blockIdx.x - 768;
        for (int i = threadIdx.x; i < 2048; i += 256) {
            int o = i >> 6, c = i & 63;
            wT[0][c][o] = curvW[i];
            wT[1][c][o] = tangW[i];
        }
        __syncthreads();

        int b    = mbid >> 2;
        int tq   = (mbid & 3) * 64 + (threadIdx.x & 63);
        int sub  = threadIdx.x >> 6;
        int feat = sub >> 1;
        int ob   = (sub & 1) * 16;

        float a[16];
#pragma unroll
        for (int j = 0; j < 16; j++) a[j] = 0.0f;

        const float* x = xb + ((size_t)(b * 3 + 1 + feat) * CDIM) * T + tq * 4;

#pragma unroll 4
        for (int c = 0; c < CDIM; c++) {
            float4 v = *(const float4*)(x + (size_t)c * T);
            float p = (v.x + v.y + v.z + v.w) * 0.25f;
#pragma unroll
            for (int j4 = 0; j4 < 4; j4++) {
                float4 w = *(const float4*)&wT[feat][c][ob + j4 * 4];
                a[j4*4+0] = fmaf(p, w.x, a[j4*4+0]);
                a[j4*4+1] = fmaf(p, w.y, a[j4*4+1]);
                a[j4*4+2] = fmaf(p, w.z, a[j4*4+2]);
                a[j4*4+3] = fmaf(p, w.w, a[j4*4+3]);
            }
        }

        float* dst = (feat == 0 ? g_curv : g_tang) +
                     (size_t)b * (TQ * 32) + (size_t)tq * 32 + ob;
#pragma unroll
        for (int j4 = 0; j4 < 4; j4++)
            *(float4*)(dst + j4 * 4) =
                make_float4(a[j4*4+0], a[j4*4+1], a[j4*4+2], a[j4*4+3]);
    }
}

// ---------------------------------------------------------------------------
// BN2 finalize (deterministic fixed-order).
// ---------------------------------------------------------------------------
__global__ void k_bnfin(const float* __restrict__ sump,
                        const float* __restrict__ sqp, int np,
                        const float* __restrict__ gamma,
                        const float* __restrict__ beta,
                        float* __restrict__ scale,
                        float* __restrict__ shift) {
    int ch = blockIdx.x;
    float s = 0.0f, q = 0.0f;
    for (int i = threadIdx.x; i < np; i += 256) {
        s += sump[ch * np + i];
        q += sqp [ch * np + i];
    }
    __shared__ float rs[8], rq[8];
    int w = threadIdx.x >> 5, lane = threadIdx.x & 31;
#pragma unroll
    for (int off = 16; off > 0; off >>= 1) {
        s += __shfl_xor_sync(0xffffffffu, s, off);
        q += __shfl_xor_sync(0xffffffffu, q, off);
    }
    if (lane == 0) { rs[w] = s; rq[w] = q; }
    __syncthreads();
    if (threadIdx.x == 0) {
        float S = 0.0f, Q = 0.0f;
#pragma unroll
        for (int ww = 0; ww < 8; ww++) { S += rs[ww]; Q += rq[ww]; }
        float mean = S * (1.0f / BT);
        float var  = fmaxf(Q * (1.0f / BT) - mean * mean, 0.0f);
        float sc   = gamma[ch] * rsqrtf(var + 1e-5f);
        scale[ch]  = sc;
        shift[ch]  = beta[ch] - mean * sc;
    }
}

// ---------------------------------------------------------------------------
// K_conv: BN2+ELU + dw15 + pw(24->32). No reductions (stats in k_pwstats).
// grid 1024 (64-t tiles), 256 thr.
// ---------------------------------------------------------------------------
__global__ void __launch_bounds__(256)
k_conv(const float* __restrict__ dwW,
       const float* __restrict__ pwW) {
    __shared__ float sh[24][80];         // 78 used (64 + 14 halo)
    __shared__ float sdw[24][16];
    __shared__ float spw[32][24];
    __shared__ float dwv[24][68];        // 64 used

    int b   = blockIdx.x >> 4;
    int t0  = (blockIdx.x & 15) * 64;
    int tid = threadIdx.x;

    for (int i = tid; i < 360; i += 256) sdw[i / 15][i % 15] = dwW[i];
    for (int i = tid; i < 768; i += 256) spw[i / 24][i % 24] = pwW[i];

    for (int i = tid; i < 24 * 78; i += 256) {
        int ch = i / 78, j = i % 78;
        int t = t0 + j - 7;
        float v = 0.0f;
        if (t >= 0 && t < T) {
            float raw = g_s[(size_t)ch * BT + b * T + t];
            v = eluf(fmaf(raw, g_bn2_scale[ch], g_bn2_shift[ch]));
        }
        sh[ch][j] = v;
    }
    __syncthreads();

    // depthwise: thread = (t-pair, ch-group of 3)
    {
        int tp = tid & 31;
        int cg = tid >> 5;
#pragma unroll
        for (int cc = 0; cc < 3; cc++) {
            int ch = cg * 3 + cc;
            float s[18];
#pragma unroll
            for (int j = 0; j < 9; j++) {
                float2 v = *(const float2*)&sh[ch][2 * tp + 2 * j];
                s[2*j] = v.x; s[2*j+1] = v.y;
            }
            float a0 = 0.0f, a1 = 0.0f;
#pragma unroll
            for (int k = 0; k < 15; k++) {
                float w = sdw[ch][k];
                a0 = fmaf(s[k],     w, a0);
                a1 = fmaf(s[k + 1], w, a1);
            }
            *(float2*)&dwv[ch][2 * tp] = make_float2(a0, a1);
        }
    }
    __syncthreads();

    // pointwise: thread = (t, o-group of 8)
    int tl = tid & 63;
    int og = tid >> 6;
    float dreg[24];
#pragma unroll
    for (int ch = 0; ch < 24; ch++) dreg[ch] = dwv[ch][tl];

    int t = t0 + tl;
#pragma unroll
    for (int oo = 0; oo < 8; oo++) {
        int o = og * 8 + oo;
        float a = 0.0f;
#pragma unroll
        for (int c4 = 0; c4 < 6; c4++) {
            float4 w = *(const float4*)&spw[o][c4 * 4];
            a = fmaf(dreg[c4*4+0], w.x, a);
            a = fmaf(dreg[c4*4+1], w.y, a);
            a = fmaf(dreg[c4*4+2], w.z, a);
            a = fmaf(dreg[c4*4+3], w.w, a);
        }
        g_pw[(size_t)o * BT + b * T + t] = a;
    }
}

// ---------------------------------------------------------------------------
// K_pwstats: BN1 partials over g_pw. Block = (ch, seg of 4096 floats).
// Deterministic per-block tree. Writes g_cp_[ch*16+seg].
// ---------------------------------------------------------------------------
__global__ void __launch_bounds__(256)
k_pwstats() {
    int ch  = blockIdx.x >> 4;
    int seg = blockIdx.x & 15;
    const float4* p = (const float4*)(g_pw + (size_t)ch * BT + seg * 4096);

    float s = 0.0f, q = 0.0f;
#pragma unroll
    for (int j = 0; j < 4; j++) {
        float4 v = p[threadIdx.x + 256 * j];
        s += v.x + v.y + v.z + v.w;
        q += v.x*v.x + v.y*v.y + v.z*v.z + v.w*v.w;
    }
    __shared__ float rs[8], rq[8];
    int w = threadIdx.x >> 5, lane = threadIdx.x & 31;
#pragma unroll
    for (int off = 16; off > 0; off >>= 1) {
        s += __shfl_xor_sync(0xffffffffu, s, off);
        q += __shfl_xor_sync(0xffffffffu, q, off);
    }
    if (lane == 0) { rs[w] = s; rq[w] = q; }
    __syncthreads();
    if (threadIdx.x == 0) {
        float S = 0.0f, Q = 0.0f;
#pragma unroll
        for (int ww = 0; ww < 8; ww++) { S += rs[ww]; Q += rq[ww]; }
        g_cp_sum[ch * 16 + seg] = S;
        g_cp_sq [ch * 16 + seg] = Q;
    }
}

// ---------------------------------------------------------------------------
// K_scan: per-block bn1 finalize (redundant, deterministic) + BN1+ELU+pool4
// into shared + warp-0 LIF scan + FC. 64 blocks x 256 thr.
// ---------------------------------------------------------------------------
__global__ void __launch_bounds__(256)
k_scan(const float* __restrict__ bn1_g,
       const float* __restrict__ bn1_b,
       const float* __restrict__ tau_geo,
       const float* __restrict__ beta_m,
       const float* __restrict__ alpha,
       const float* __restrict__ gamma_p,
       const float* __restrict__ fcW,
       const float* __restrict__ fcb,
       float* __restrict__ out) {
    __shared__ float sx[256][33];     // [tq][o], padded
    __shared__ float ssc[32], ssh[32];

    int b   = blockIdx.x;
    int tid = threadIdx.x;

    // bn1 finalize: thread = (ch = tid>>3, part = tid&7), 2 partials each.
    {
        int ch = tid >> 3, p = tid & 7;
        float s = g_cp_sum[ch * 16 + p * 2] + g_cp_sum[ch * 16 + p * 2 + 1];
        float q = g_cp_sq [ch * 16 + p * 2] + g_cp_sq [ch * 16 + p * 2 + 1];
#pragma unroll
        for (int off = 4; off > 0; off >>= 1) {
            s += __shfl_xor_sync(0xffffffffu, s, off);
            q += __shfl_xor_sync(0xffffffffu, q, off);
        }
        if (p == 0) {
            float mean = s * (1.0f / BT);
            float var  = fmaxf(q * (1.0f / BT) - mean * mean, 0.0f);
            float sc   = bn1_g[ch] * rsqrtf(var + 1e-5f);
            ssc[ch] = sc;
            ssh[ch] = bn1_b[ch] - mean * sc;
        }
    }
    __syncthreads();

    // prelif: thread = (o = tid>>3, lane p = tid&7); tq = p + 8k, coalesced.
    {
        int o = tid >> 3, p = tid & 7;
        const float4* src = (const float4*)(g_pw + (size_t)o * BT + b * T);
        float sc = ssc[o], shf = ssh[o];
#pragma unroll 4
        for (int k = 0; k < 32; k++) {
            int tq = p + 8 * k;
            float4 v = src[tq];
            float y0 = eluf(fmaf(v.x, sc, shf));
            float y1 = eluf(fmaf(v.y, sc, shf));
            float y2 = eluf(fmaf(v.z, sc, shf));
            float y3 = eluf(fmaf(v.w, sc, shf));
            sx[tq][o] = (y0 + y1 + y2 + y3) * 0.25f;
        }
    }
    __syncthreads();

    if (tid < 32) {
        int o = tid;
        float tau    = 1.0f / (1.0f + expf(-tau_geo[0]));
        float om_tau = 1.0f - tau;
        float beta   = beta_m[0];
        float al     = alpha[0];
        float gp     = gamma_p[0];

        const float* cup = g_curv + (size_t)b * (TQ * 32) + o;
        const float* tap = g_tang + (size_t)b * (TQ * 32) + o;

        float pcu[8], pta[8];
#pragma unroll
        for (int i = 0; i < 8; i++) {
            pcu[i] = cup[i * 32];
            pta[i] = tap[i * 32];
        }

        float m = 0.0f, cs = 0.0f, ts = 0.0f, fr = 0.0f;

#pragma unroll 8
        for (int tq = 0; tq < TQ; tq++) {
            int s = tq & 7;
            float cu = pcu[s], ta = pta[s];
            int nl = tq + 8; if (nl > TQ - 1) nl = TQ - 1;
            pcu[s] = cup[nl * 32];
            pta[s] = tap[nl * 32];
            float xv = sx[tq][o];

            cs = fmaf(tau, cs, om_tau * cu);
            ts = fmaf(tau, ts, om_tau * ta);
            float vth  = fmaxf(fmaf(al, cs, 0.3f), 0.1f);
            float a    = fmaf(-gp, ts, 1.0f);
            float sens = 1.0f / (1.0f + expf(-a));
            float mn   = fmaf(beta, m, xv * sens);
            float sp   = (mn - vth) > 0.0f ? 1.0f : 0.0f;
            m  = fmaf(-sp, vth, mn);
            fr += sp;
        }

        fr *= (1.0f / (float)TQ);

        float res[4];
#pragma unroll
        for (int k = 0; k < 4; k++) {
            float vv = fr * __ldg(fcW + k * 32 + o);
#pragma unroll
            for (int off = 16; off > 0; off >>= 1)
                vv += __shfl_xor_sync(0xffffffffu, vv, off);
            res[k] = vv;
        }
        if (o == 0) {
#pragma unroll
            for (int k = 0; k < 4; k++)
                out[b * 4 + k] = res[k] + __ldg(fcb + k);
        }
    }
}

// ---------------------------------------------------------------------------
extern "C" void kernel_launch(void* const* d_in, const int* in_sizes, int n_in,
                              void* d_out, int out_size) {
    const float* xb       = (const float*)d_in[0];
    const float* mu       = (const float*)d_in[1];
    const float* sigma    = (const float*)d_in[2];
    const float* curvW    = (const float*)d_in[3];
    const float* tangW    = (const float*)d_in[4];
    const float* spatialW = (const float*)d_in[5];
    const float* bn2_g    = (const float*)d_in[6];
    const float* bn2_b    = (const float*)d_in[7];
    const float* dwW      = (const float*)d_in[8];
    const float* pwW      = (const float*)d_in[9];
    const float* bn1_g    = (const float*)d_in[10];
    const float* bn1_b    = (const float*)d_in[11];
    const float* tau_geo  = (const float*)d_in[12];
    const float* beta_m   = (const float*)d_in[13];
    const float* alpha    = (const float*)d_in[14];
    const float* gamma_p  = (const float*)d_in[15];
    const float* fcW      = (const float*)d_in[16];
    const float* fcb      = (const float*)d_in[17];
    float* out            = (float*)d_out;

    float* ep_s;  cudaGetSymbolAddress((void**)&ep_s,  g_ep_sum);
    float* ep_q;  cudaGetSymbolAddress((void**)&ep_q,  g_ep_sq);
    float* bn2sc; cudaGetSymbolAddress((void**)&bn2sc, g_bn2_scale);
    float* bn2sh; cudaGetSymbolAddress((void**)&bn2sh, g_bn2_shift);

    k_front<<<1024, 256>>>(xb, curvW, tangW, mu, sigma, spatialW);
    k_bnfin<<<24, 256>>>(ep_s, ep_q, NCTA_ENC, bn2_g, bn2_b, bn2sc, bn2sh);
    k_conv<<<1024, 256>>>(dwW, pwW);
    k_pwstats<<<512, 256>>>();
    k_scan<<<64, 256>>>(bn1_g, bn1_b, tau_geo, beta_m, alpha, gamma_p,
                        fcW, fcb, out);
}

// round 7
// speedup vs baseline: 3.0465x; 1.0226x over previous
#include <cuda_runtime.h>
#include <cstdint>

// ---------------------------------------------------------------------------
// GeoEEGSNN forward: B=64, C=64, T=1024, Tq=256. 5 launches:
//   k_front  : [0..383] encode (ratio trick, __expf, 2t/thread) + BN2 partials
//              [384..639] curv/tang mapper (pool4 first)
//   k_bnfin  : bn2 scale/shift finalize
//   k_conv   : BN2+ELU + dw15 + pw(24->32)          -> g_pw [o][b*T+t]
//   k_pwstats: vectorized BN1 partials (32ch x 8 seg)
//   k_scan   : bn1 finalize + BN1+ELU+pool4 (smem) + LIF scan + FC
// ---------------------------------------------------------------------------

#define B 64
#define CDIM 64
#define T 1024
#define BT (B*T)           // 65536
#define TQ 256
#define NCTA_ENC 128       // partial blocks per feature

__device__ float g_s [24 * BT];
__device__ float g_pw[32 * BT];
__device__ float g_curv[B * TQ * 32];   // [b][tq][o]
__device__ float g_tang[B * TQ * 32];
__device__ float g_ep_sum[24 * NCTA_ENC], g_ep_sq[24 * NCTA_ENC];
__device__ float g_cp_sum[32 * 8],        g_cp_sq[32 * 8];
__device__ float g_bn2_scale[24], g_bn2_shift[24];

__device__ __forceinline__ float eluf(float x) {
    return x > 0.0f ? x : (__expf(x) - 1.0f);
}

// ---------------------------------------------------------------------------
// K_front: fat kernel. Blocks [0,384): encode (2 t per thread);
// [384,640): mapper. Shared aliased.
// ---------------------------------------------------------------------------
__global__ void __launch_bounds__(256)
k_front(const float* __restrict__ xb,
        const float* __restrict__ curvW,
        const float* __restrict__ tangW,
        const float* __restrict__ mu,
        const float* __restrict__ sigma,
        const float* __restrict__ spatialW) {
    __shared__ __align__(16) char smem[16896];

    if (blockIdx.x < 384) {
        // ---------------- encode ----------------
        float2 (*sw)[64]   = (float2(*)[64])smem;            // 2048 B
        float  (*red_s)[8] = (float(*)[8])(smem + 2048);
        float  (*red_q)[8] = (float(*)[8])(smem + 2304);

        int f   = blockIdx.x / 128;       // 0..2
        int blk = blockIdx.x - f * 128;   // 0..127
        int b     = blk >> 1;
        int thalf = blk & 1;

        float smu[4], sg[4];
#pragma unroll
        for (int p = 0; p < 4; p++) { smu[p] = __ldg(mu + p); sg[p] = __ldg(sigma + p); }
        float d = smu[1] - smu[0];
        bool uni = (fabsf((smu[2] - smu[1]) - d) <= 1e-5f * fmaxf(1.0f, fabsf(d))) &&
                   (fabsf((smu[3] - smu[2]) - d) <= 1e-5f * fmaxf(1.0f, fabsf(d))) &&
                   (fabsf(sg[1] - sg[0]) <= 1e-6f) &&
                   (fabsf(sg[2] - sg[0]) <= 1e-6f) &&
                   (fabsf(sg[3] - sg[0]) <= 1e-6f);
        float q    = -1.0f / (2.0f * sg[0] * sg[0] + 1e-6f);
        float m0   = smu[0];
        float n2qd = -2.0f * q * d;

        {
            int i = threadIdx.x;
            int p = i >> 6, c = i & 63;
            int g = f * 4 + p;
            float cp = uni ? expf(q * (float)(p * p) * d * d) : 1.0f;
            sw[p][c] = make_float2(spatialW[(g * 2 + 0) * 64 + c] * cp,
                                   spatialW[(g * 2 + 1) * 64 + c] * cp);
        }
        __syncthreads();

        int t = thalf * 512 + threadIdx.x * 2;

        float acc0[8], acc1[8];
#pragma unroll
        for (int i = 0; i < 8; i++) { acc0[i] = 0.0f; acc1[i] = 0.0f; }

        const float* xp = xb + ((size_t)(b * 3 + f) * CDIM) * T + t;

        if (uni) {
#pragma unroll 4
            for (int c = 0; c < CDIM; c++) {
                float2 xv = *(const float2*)(xp + (size_t)c * T);
                float dx0 = xv.x - m0;
                float dx1 = xv.y - m0;
                float e00 = __expf(q * dx0 * dx0);
                float r0  = __expf(n2qd * dx0);
                float e10 = __expf(q * dx1 * dx1);
                float r1  = __expf(n2qd * dx1);
                float a0 = e00, a1 = e10;
#pragma unroll
                for (int p = 0; p < 4; p++) {
                    float2 w = sw[p][c];
                    acc0[p*2+0] = fmaf(a0, w.x, acc0[p*2+0]);
                    acc0[p*2+1] = fmaf(a0, w.y, acc0[p*2+1]);
                    acc1[p*2+0] = fmaf(a1, w.x, acc1[p*2+0]);
                    acc1[p*2+1] = fmaf(a1, w.y, acc1[p*2+1]);
                    a0 *= r0;
                    a1 *= r1;
                }
            }
        } else {
            float sneg[4];
#pragma unroll
            for (int p = 0; p < 4; p++) sneg[p] = -1.0f / (2.0f * sg[p] * sg[p] + 1e-6f);
#pragma unroll 2
            for (int c = 0; c < CDIM; c++) {
                float2 xv = *(const float2*)(xp + (size_t)c * T);
#pragma unroll
                for (int p = 0; p < 4; p++) {
                    float dx0 = xv.x - smu[p];
                    float dx1 = xv.y - smu[p];
                    float e0 = expf(dx0 * dx0 * sneg[p]);
                    float e1 = expf(dx1 * dx1 * sneg[p]);
                    float2 w = sw[p][c];
                    acc0[p*2+0] = fmaf(e0, w.x, acc0[p*2+0]);
                    acc0[p*2+1] = fmaf(e0, w.y, acc0[p*2+1]);
                    acc1[p*2+0] = fmaf(e1, w.x, acc1[p*2+0]);
                    acc1[p*2+1] = fmaf(e1, w.y, acc1[p*2+1]);
                }
            }
        }

#pragma unroll
        for (int cc = 0; cc < 8; cc++)
            *(float2*)(g_s + (size_t)(f * 8 + cc) * BT + b * T + t) =
                make_float2(acc0[cc], acc1[cc]);

        int w = threadIdx.x >> 5, lane = threadIdx.x & 31;
#pragma unroll
        for (int cc = 0; cc < 8; cc++) {
            float s  = acc0[cc] + acc1[cc];
            float qv = acc0[cc] * acc0[cc] + acc1[cc] * acc1[cc];
#pragma unroll
            for (int off = 16; off > 0; off >>= 1) {
                s  += __shfl_xor_sync(0xffffffffu, s, off);
                qv += __shfl_xor_sync(0xffffffffu, qv, off);
            }
            if (lane == 0) { red_s[w][cc] = s; red_q[w][cc] = qv; }
        }
        __syncthreads();
        if (threadIdx.x < 8) {
            float S = 0.0f, Q = 0.0f;
#pragma unroll
            for (int ww = 0; ww < 8; ww++) { S += red_s[ww][threadIdx.x]; Q += red_q[ww][threadIdx.x]; }
            g_ep_sum[(f * 8 + threadIdx.x) * NCTA_ENC + blk] = S;
            g_ep_sq [(f * 8 + threadIdx.x) * NCTA_ENC + blk] = Q;
        }
    } else {
        // ---------------- mapper ----------------
        float (*wT)[64][32] = (float(*)[64][32])smem;   // 16KB

        int mbid = blockIdx.x - 384;
        for (int i = threadIdx.x; i < 2048; i += 256) {
            int o = i >> 6, c = i & 63;
            wT[0][c][o] = curvW[i];
            wT[1][c][o] = tangW[i];
        }
        __syncthreads();

        int b    = mbid >> 2;
        int tq   = (mbid & 3) * 64 + (threadIdx.x & 63);
        int sub  = threadIdx.x >> 6;
        int feat = sub >> 1;
        int ob   = (sub & 1) * 16;

        float a[16];
#pragma unroll
        for (int j = 0; j < 16; j++) a[j] = 0.0f;

        const float* x = xb + ((size_t)(b * 3 + 1 + feat) * CDIM) * T + tq * 4;

#pragma unroll 4
        for (int c = 0; c < CDIM; c++) {
            float4 v = *(const float4*)(x + (size_t)c * T);
            float p = (v.x + v.y + v.z + v.w) * 0.25f;
#pragma unroll
            for (int j4 = 0; j4 < 4; j4++) {
                float4 w = *(const float4*)&wT[feat][c][ob + j4 * 4];
                a[j4*4+0] = fmaf(p, w.x, a[j4*4+0]);
                a[j4*4+1] = fmaf(p, w.y, a[j4*4+1]);
                a[j4*4+2] = fmaf(p, w.z, a[j4*4+2]);
                a[j4*4+3] = fmaf(p, w.w, a[j4*4+3]);
            }
        }

        float* dst = (feat == 0 ? g_curv : g_tang) +
                     (size_t)b * (TQ * 32) + (size_t)tq * 32 + ob;
#pragma unroll
        for (int j4 = 0; j4 < 4; j4++)
            *(float4*)(dst + j4 * 4) =
                make_float4(a[j4*4+0], a[j4*4+1], a[j4*4+2], a[j4*4+3]);
    }
}

// ---------------------------------------------------------------------------
// BN2 finalize (deterministic fixed-order).
// ---------------------------------------------------------------------------
__global__ void k_bnfin(const float* __restrict__ sump,
                        const float* __restrict__ sqp, int np,
                        const float* __restrict__ gamma,
                        const float* __restrict__ beta,
                        float* __restrict__ scale,
                        float* __restrict__ shift) {
    int ch = blockIdx.x;
    float s = 0.0f, q = 0.0f;
    for (int i = threadIdx.x; i < np; i += 256) {
        s += sump[ch * np + i];
        q += sqp [ch * np + i];
    }
    __shared__ float rs[8], rq[8];
    int w = threadIdx.x >> 5, lane = threadIdx.x & 31;
#pragma unroll
    for (int off = 16; off > 0; off >>= 1) {
        s += __shfl_xor_sync(0xffffffffu, s, off);
        q += __shfl_xor_sync(0xffffffffu, q, off);
    }
    if (lane == 0) { rs[w] = s; rq[w] = q; }
    __syncthreads();
    if (threadIdx.x == 0) {
        float S = 0.0f, Q = 0.0f;
#pragma unroll
        for (int ww = 0; ww < 8; ww++) { S += rs[ww]; Q += rq[ww]; }
        float mean = S * (1.0f / BT);
        float var  = fmaxf(Q * (1.0f / BT) - mean * mean, 0.0f);
        float sc   = gamma[ch] * rsqrtf(var + 1e-5f);
        scale[ch]  = sc;
        shift[ch]  = beta[ch] - mean * sc;
    }
}

// ---------------------------------------------------------------------------
// K_conv: BN2+ELU + dw15 + pw(24->32). grid 1024 (64-t tiles), 256 thr.
// ---------------------------------------------------------------------------
__global__ void __launch_bounds__(256)
k_conv(const float* __restrict__ dwW,
       const float* __restrict__ pwW) {
    __shared__ float sh[24][80];         // 78 used (64 + 14 halo)
    __shared__ float sdw[24][16];
    __shared__ float spw[32][24];
    __shared__ float dwv[24][68];        // 64 used

    int b   = blockIdx.x >> 4;
    int t0  = (blockIdx.x & 15) * 64;
    int tid = threadIdx.x;

    for (int i = tid; i < 360; i += 256) sdw[i / 15][i % 15] = dwW[i];
    for (int i = tid; i < 768; i += 256) spw[i / 24][i % 24] = pwW[i];

    for (int i = tid; i < 24 * 78; i += 256) {
        int ch = i / 78, j = i % 78;
        int t = t0 + j - 7;
        float v = 0.0f;
        if (t >= 0 && t < T) {
            float raw = g_s[(size_t)ch * BT + b * T + t];
            v = eluf(fmaf(raw, g_bn2_scale[ch], g_bn2_shift[ch]));
        }
        sh[ch][j] = v;
    }
    __syncthreads();

    {
        int tp = tid & 31;
        int cg = tid >> 5;
#pragma unroll
        for (int cc = 0; cc < 3; cc++) {
            int ch = cg * 3 + cc;
            float s[18];
#pragma unroll
            for (int j = 0; j < 9; j++) {
                float2 v = *(const float2*)&sh[ch][2 * tp + 2 * j];
                s[2*j] = v.x; s[2*j+1] = v.y;
            }
            float a0 = 0.0f, a1 = 0.0f;
#pragma unroll
            for (int k = 0; k < 15; k++) {
                float w = sdw[ch][k];
                a0 = fmaf(s[k],     w, a0);
                a1 = fmaf(s[k + 1], w, a1);
            }
            *(float2*)&dwv[ch][2 * tp] = make_float2(a0, a1);
        }
    }
    __syncthreads();

    int tl = tid & 63;
    int og = tid >> 6;
    float dreg[24];
#pragma unroll
    for (int ch = 0; ch < 24; ch++) dreg[ch] = dwv[ch][tl];

    int t = t0 + tl;
#pragma unroll
    for (int oo = 0; oo < 8; oo++) {
        int o = og * 8 + oo;
        float a = 0.0f;
#pragma unroll
        for (int c4 = 0; c4 < 6; c4++) {
            float4 w = *(const float4*)&spw[o][c4 * 4];
            a = fmaf(dreg[c4*4+0], w.x, a);
            a = fmaf(dreg[c4*4+1], w.y, a);
            a = fmaf(dreg[c4*4+2], w.z, a);
            a = fmaf(dreg[c4*4+3], w.w, a);
        }
        g_pw[(size_t)o * BT + b * T + t] = a;
    }
}

// ---------------------------------------------------------------------------
// K_pwstats: BN1 partials. Block = (ch, seg of 8192 floats). 256 blocks.
// 8 independent float4 loads per thread (MLP 8).
// ---------------------------------------------------------------------------
__global__ void __launch_bounds__(256)
k_pwstats() {
    int ch  = blockIdx.x >> 3;
    int seg = blockIdx.x & 7;
    const float4* p = (const float4*)(g_pw + (size_t)ch * BT + seg * 8192);

    float4 v[8];
#pragma unroll
    for (int j = 0; j < 8; j++) v[j] = p[threadIdx.x + 256 * j];

    float s = 0.0f, q = 0.0f;
#pragma unroll
    for (int j = 0; j < 8; j++) {
        s += v[j].x + v[j].y + v[j].z + v[j].w;
        q += v[j].x*v[j].x + v[j].y*v[j].y + v[j].z*v[j].z + v[j].w*v[j].w;
    }
    __shared__ float rs[8], rq[8];
    int w = threadIdx.x >> 5, lane = threadIdx.x & 31;
#pragma unroll
    for (int off = 16; off > 0; off >>= 1) {
        s += __shfl_xor_sync(0xffffffffu, s, off);
        q += __shfl_xor_sync(0xffffffffu, q, off);
    }
    if (lane == 0) { rs[w] = s; rq[w] = q; }
    __syncthreads();
    if (threadIdx.x == 0) {
        float S = 0.0f, Q = 0.0f;
#pragma unroll
        for (int ww = 0; ww < 8; ww++) { S += rs[ww]; Q += rq[ww]; }
        g_cp_sum[ch * 8 + seg] = S;
        g_cp_sq [ch * 8 + seg] = Q;
    }
}

// ---------------------------------------------------------------------------
// K_scan: per-block bn1 finalize + BN1+ELU+pool4 (smem) + warp-0 LIF + FC.
// ---------------------------------------------------------------------------
__global__ void __launch_bounds__(256)
k_scan(const float* __restrict__ bn1_g,
       const float* __restrict__ bn1_b,
       const float* __restrict__ tau_geo,
       const float* __restrict__ beta_m,
       const float* __restrict__ alpha,
       const float* __restrict__ gamma_p,
       const float* __restrict__ fcW,
       const float* __restrict__ fcb,
       float* __restrict__ out) {
    __shared__ float sx[256][33];
    __shared__ float ssc[32], ssh[32];

    int b   = blockIdx.x;
    int tid = threadIdx.x;

    // bn1 finalize: ch = tid>>3, one partial per lane p = tid&7.
    {
        int ch = tid >> 3, p = tid & 7;
        float s = g_cp_sum[ch * 8 + p];
        float q = g_cp_sq [ch * 8 + p];
#pragma unroll
        for (int off = 4; off > 0; off >>= 1) {
            s += __shfl_xor_sync(0xffffffffu, s, off);
            q += __shfl_xor_sync(0xffffffffu, q, off);
        }
        if (p == 0) {
            float mean = s * (1.0f / BT);
            float var  = fmaxf(q * (1.0f / BT) - mean * mean, 0.0f);
            float sc   = bn1_g[ch] * rsqrtf(var + 1e-5f);
            ssc[ch] = sc;
            ssh[ch] = bn1_b[ch] - mean * sc;
        }
    }
    __syncthreads();

    {
        int o = tid >> 3, p = tid & 7;
        const float4* src = (const float4*)(g_pw + (size_t)o * BT + b * T);
        float sc = ssc[o], shf = ssh[o];
#pragma unroll 4
        for (int k = 0; k < 32; k++) {
            int tq = p + 8 * k;
            float4 v = src[tq];
            float y0 = eluf(fmaf(v.x, sc, shf));
            float y1 = eluf(fmaf(v.y, sc, shf));
            float y2 = eluf(fmaf(v.z, sc, shf));
            float y3 = eluf(fmaf(v.w, sc, shf));
            sx[tq][o] = (y0 + y1 + y2 + y3) * 0.25f;
        }
    }
    __syncthreads();

    if (tid < 32) {
        int o = tid;
        float tau    = 1.0f / (1.0f + expf(-tau_geo[0]));
        float om_tau = 1.0f - tau;
        float beta   = beta_m[0];
        float al     = alpha[0];
        float gp     = gamma_p[0];

        const float* cup = g_curv + (size_t)b * (TQ * 32) + o;
        const float* tap = g_tang + (size_t)b * (TQ * 32) + o;

        float pcu[8], pta[8];
#pragma unroll
        for (int i = 0; i < 8; i++) {
            pcu[i] = cup[i * 32];
            pta[i] = tap[i * 32];
        }

        float m = 0.0f, cs = 0.0f, ts = 0.0f, fr = 0.0f;

#pragma unroll 8
        for (int tq = 0; tq < TQ; tq++) {
            int s = tq & 7;
            float cu = pcu[s], ta = pta[s];
            int nl = tq + 8; if (nl > TQ - 1) nl = TQ - 1;
            pcu[s] = cup[nl * 32];
            pta[s] = tap[nl * 32];
            float xv = sx[tq][o];

            cs = fmaf(tau, cs, om_tau * cu);
            ts = fmaf(tau, ts, om_tau * ta);
            float vth  = fmaxf(fmaf(al, cs, 0.3f), 0.1f);
            float a    = fmaf(-gp, ts, 1.0f);
            float sens = 1.0f / (1.0f + expf(-a));
            float mn   = fmaf(beta, m, xv * sens);
            float sp   = (mn - vth) > 0.0f ? 1.0f : 0.0f;
            m  = fmaf(-sp, vth, mn);
            fr += sp;
        }

        fr *= (1.0f / (float)TQ);

        float res[4];
#pragma unroll
        for (int k = 0; k < 4; k++) {
            float vv = fr * __ldg(fcW + k * 32 + o);
#pragma unroll
            for (int off = 16; off > 0; off >>= 1)
                vv += __shfl_xor_sync(0xffffffffu, vv, off);
            res[k] = vv;
        }
        if (o == 0) {
#pragma unroll
            for (int k = 0; k < 4; k++)
                out[b * 4 + k] = res[k] + __ldg(fcb + k);
        }
    }
}

// ---------------------------------------------------------------------------
extern "C" void kernel_launch(void* const* d_in, const int* in_sizes, int n_in,
                              void* d_out, int out_size) {
    const float* xb       = (const float*)d_in[0];
    const float* mu       = (const float*)d_in[1];
    const float* sigma    = (const float*)d_in[2];
    const float* curvW    = (const float*)d_in[3];
    const float* tangW    = (const float*)d_in[4];
    const float* spatialW = (const float*)d_in[5];
    const float* bn2_g    = (const float*)d_in[6];
    const float* bn2_b    = (const float*)d_in[7];
    const float* dwW      = (const float*)d_in[8];
    const float* pwW      = (const float*)d_in[9];
    const float* bn1_g    = (const float*)d_in[10];
    const float* bn1_b    = (const float*)d_in[11];
    const float* tau_geo  = (const float*)d_in[12];
    const float* beta_m   = (const float*)d_in[13];
    const float* alpha    = (const float*)d_in[14];
    const float* gamma_p  = (const float*)d_in[15];
    const float* fcW      = (const float*)d_in[16];
    const float* fcb      = (const float*)d_in[17];
    float* out            = (float*)d_out;

    float* ep_s;  cudaGetSymbolAddress((void**)&ep_s,  g_ep_sum);
    float* ep_q;  cudaGetSymbolAddress((void**)&ep_q,  g_ep_sq);
    float* bn2sc; cudaGetSymbolAddress((void**)&bn2sc, g_bn2_scale);
    float* bn2sh; cudaGetSymbolAddress((void**)&bn2sh, g_bn2_shift);

    k_front<<<640, 256>>>(xb, curvW, tangW, mu, sigma, spatialW);
    k_bnfin<<<24, 256>>>(ep_s, ep_q, NCTA_ENC, bn2_g, bn2_b, bn2sc, bn2sh);
    k_conv<<<1024, 256>>>(dwW, pwW);
    k_pwstats<<<256, 256>>>();
    k_scan<<<64, 256>>>(bn1_g, bn1_b, tau_geo, beta_m, alpha, gamma_p,
                        fcW, fcb, out);
}

// round 8
// speedup vs baseline: 4.0211x; 1.3199x over previous
#include <cuda_runtime.h>
#include <cstdint>

// ---------------------------------------------------------------------------
// GeoEEGSNN forward: B=64, C=64, T=1024, Tq=256. 4 launches:
//   k_front  : [0..383] encode (ratio trick, __expf) + BN2 partials
//              [384..639] curv/tang mapper (pool4 first)
//   k_conv   : inline BN2 finalize + BN2+ELU + dw15 + pw(24->32) -> g_pw
//   k_pwstats: vectorized BN1 partials (32ch x 8 seg)
//   k_scan   : bn1 finalize + prelif + parallel cs/ts + serial m + FC
// ---------------------------------------------------------------------------

#define B 64
#define CDIM 64
#define T 1024
#define BT (B*T)           // 65536
#define TQ 256
#define NCTA_ENC 128       // partial blocks per feature

__device__ float g_s [24 * BT];
__device__ float g_pw[32 * BT];
__device__ float g_curv[B * TQ * 32];   // [b][tq][o]
__device__ float g_tang[B * TQ * 32];
__device__ float g_ep_sum[24 * NCTA_ENC], g_ep_sq[24 * NCTA_ENC];
__device__ float g_cp_sum[32 * 8],        g_cp_sq[32 * 8];

__device__ __forceinline__ float eluf(float x) {
    return x > 0.0f ? x : (__expf(x) - 1.0f);
}

// ---------------------------------------------------------------------------
// K_front: fat kernel. Blocks [0,384): encode (2 t/thread);
// [384,640): mapper. Shared aliased.
// ---------------------------------------------------------------------------
__global__ void __launch_bounds__(256)
k_front(const float* __restrict__ xb,
        const float* __restrict__ curvW,
        const float* __restrict__ tangW,
        const float* __restrict__ mu,
        const float* __restrict__ sigma,
        const float* __restrict__ spatialW) {
    __shared__ __align__(16) char smem[16896];

    if (blockIdx.x < 384) {
        // ---------------- encode ----------------
        // swq[c][0] = (w_p0.x, w_p0.y, w_p1.x, w_p1.y); swq[c][1] = p2, p3.
        float4 (*swq)[2]   = (float4(*)[2])smem;             // 2048 B
        float  (*red_s)[8] = (float(*)[8])(smem + 2048);
        float  (*red_q)[8] = (float(*)[8])(smem + 2304);

        int f   = blockIdx.x / 128;       // 0..2
        int blk = blockIdx.x - f * 128;   // 0..127
        int b     = blk >> 1;
        int thalf = blk & 1;

        float smu[4], sg[4];
#pragma unroll
        for (int p = 0; p < 4; p++) { smu[p] = __ldg(mu + p); sg[p] = __ldg(sigma + p); }
        float d = smu[1] - smu[0];
        bool uni = (fabsf((smu[2] - smu[1]) - d) <= 1e-5f * fmaxf(1.0f, fabsf(d))) &&
                   (fabsf((smu[3] - smu[2]) - d) <= 1e-5f * fmaxf(1.0f, fabsf(d))) &&
                   (fabsf(sg[1] - sg[0]) <= 1e-6f) &&
                   (fabsf(sg[2] - sg[0]) <= 1e-6f) &&
                   (fabsf(sg[3] - sg[0]) <= 1e-6f);
        float q    = -1.0f / (2.0f * sg[0] * sg[0] + 1e-6f);
        float m0   = smu[0];
        float n2qd = -2.0f * q * d;

        {
            int i = threadIdx.x;             // 256 = 4p x 64c
            int p = i >> 6, c = i & 63;
            int g = f * 4 + p;
            float cp = uni ? expf(q * (float)(p * p) * d * d) : 1.0f;
            float* base = (float*)swq;
            base[c * 8 + p * 2 + 0] = spatialW[(g * 2 + 0) * 64 + c] * cp;
            base[c * 8 + p * 2 + 1] = spatialW[(g * 2 + 1) * 64 + c] * cp;
        }
        __syncthreads();

        int t = thalf * 512 + threadIdx.x * 2;

        float acc0[8], acc1[8];
#pragma unroll
        for (int i = 0; i < 8; i++) { acc0[i] = 0.0f; acc1[i] = 0.0f; }

        const float* xp = xb + ((size_t)(b * 3 + f) * CDIM) * T + t;

        if (uni) {
#pragma unroll 4
            for (int c = 0; c < CDIM; c++) {
                float2 xv = *(const float2*)(xp + (size_t)c * T);
                float dx0 = xv.x - m0;
                float dx1 = xv.y - m0;
                float a0 = __expf(q * dx0 * dx0);
                float r0 = __expf(n2qd * dx0);
                float a1 = __expf(q * dx1 * dx1);
                float r1 = __expf(n2qd * dx1);
                float4 wA = swq[c][0];
                float4 wB = swq[c][1];
                acc0[0] = fmaf(a0, wA.x, acc0[0]);
                acc0[1] = fmaf(a0, wA.y, acc0[1]);
                acc1[0] = fmaf(a1, wA.x, acc1[0]);
                acc1[1] = fmaf(a1, wA.y, acc1[1]);
                a0 *= r0; a1 *= r1;
                acc0[2] = fmaf(a0, wA.z, acc0[2]);
                acc0[3] = fmaf(a0, wA.w, acc0[3]);
                acc1[2] = fmaf(a1, wA.z, acc1[2]);
                acc1[3] = fmaf(a1, wA.w, acc1[3]);
                a0 *= r0; a1 *= r1;
                acc0[4] = fmaf(a0, wB.x, acc0[4]);
                acc0[5] = fmaf(a0, wB.y, acc0[5]);
                acc1[4] = fmaf(a1, wB.x, acc1[4]);
                acc1[5] = fmaf(a1, wB.y, acc1[5]);
                a0 *= r0; a1 *= r1;
                acc0[6] = fmaf(a0, wB.z, acc0[6]);
                acc0[7] = fmaf(a0, wB.w, acc0[7]);
                acc1[6] = fmaf(a1, wB.z, acc1[6]);
                acc1[7] = fmaf(a1, wB.w, acc1[7]);
            }
        } else {
            float sneg[4];
#pragma unroll
            for (int p = 0; p < 4; p++) sneg[p] = -1.0f / (2.0f * sg[p] * sg[p] + 1e-6f);
#pragma unroll 2
            for (int c = 0; c < CDIM; c++) {
                float2 xv = *(const float2*)(xp + (size_t)c * T);
                float4 wA = swq[c][0];
                float4 wB = swq[c][1];
                float wx[4] = {wA.x, wA.z, wB.x, wB.z};
                float wy[4] = {wA.y, wA.w, wB.y, wB.w};
#pragma unroll
                for (int p = 0; p < 4; p++) {
                    float dx0 = xv.x - smu[p];
                    float dx1 = xv.y - smu[p];
                    float e0 = expf(dx0 * dx0 * sneg[p]);
                    float e1 = expf(dx1 * dx1 * sneg[p]);
                    acc0[p*2+0] = fmaf(e0, wx[p], acc0[p*2+0]);
                    acc0[p*2+1] = fmaf(e0, wy[p], acc0[p*2+1]);
                    acc1[p*2+0] = fmaf(e1, wx[p], acc1[p*2+0]);
                    acc1[p*2+1] = fmaf(e1, wy[p], acc1[p*2+1]);
                }
            }
        }

#pragma unroll
        for (int cc = 0; cc < 8; cc++)
            *(float2*)(g_s + (size_t)(f * 8 + cc) * BT + b * T + t) =
                make_float2(acc0[cc], acc1[cc]);

        int w = threadIdx.x >> 5, lane = threadIdx.x & 31;
#pragma unroll
        for (int cc = 0; cc < 8; cc++) {
            float s  = acc0[cc] + acc1[cc];
            float qv = acc0[cc] * acc0[cc] + acc1[cc] * acc1[cc];
#pragma unroll
            for (int off = 16; off > 0; off >>= 1) {
                s  += __shfl_xor_sync(0xffffffffu, s, off);
                qv += __shfl_xor_sync(0xffffffffu, qv, off);
            }
            if (lane == 0) { red_s[w][cc] = s; red_q[w][cc] = qv; }
        }
        __syncthreads();
        if (threadIdx.x < 8) {
            float S = 0.0f, Q = 0.0f;
#pragma unroll
            for (int ww = 0; ww < 8; ww++) { S += red_s[ww][threadIdx.x]; Q += red_q[ww][threadIdx.x]; }
            g_ep_sum[(f * 8 + threadIdx.x) * NCTA_ENC + blk] = S;
            g_ep_sq [(f * 8 + threadIdx.x) * NCTA_ENC + blk] = Q;
        }
    } else {
        // ---------------- mapper ----------------
        float (*wT)[64][32] = (float(*)[64][32])smem;   // 16KB

        int mbid = blockIdx.x - 384;
        for (int i = threadIdx.x; i < 2048; i += 256) {
            int o = i >> 6, c = i & 63;
            wT[0][c][o] = curvW[i];
            wT[1][c][o] = tangW[i];
        }
        __syncthreads();

        int b    = mbid >> 2;
        int tq   = (mbid & 3) * 64 + (threadIdx.x & 63);
        int sub  = threadIdx.x >> 6;
        int feat = sub >> 1;
        int ob   = (sub & 1) * 16;

        float a[16];
#pragma unroll
        for (int j = 0; j < 16; j++) a[j] = 0.0f;

        const float* x = xb + ((size_t)(b * 3 + 1 + feat) * CDIM) * T + tq * 4;

#pragma unroll 4
        for (int c = 0; c < CDIM; c++) {
            float4 v = *(const float4*)(x + (size_t)c * T);
            float p = (v.x + v.y + v.z + v.w) * 0.25f;
#pragma unroll
            for (int j4 = 0; j4 < 4; j4++) {
                float4 w = *(const float4*)&wT[feat][c][ob + j4 * 4];
                a[j4*4+0] = fmaf(p, w.x, a[j4*4+0]);
                a[j4*4+1] = fmaf(p, w.y, a[j4*4+1]);
                a[j4*4+2] = fmaf(p, w.z, a[j4*4+2]);
                a[j4*4+3] = fmaf(p, w.w, a[j4*4+3]);
            }
        }

        float* dst = (feat == 0 ? g_curv : g_tang) +
                     (size_t)b * (TQ * 32) + (size_t)tq * 32 + ob;
#pragma unroll
        for (int j4 = 0; j4 < 4; j4++)
            *(float4*)(dst + j4 * 4) =
                make_float4(a[j4*4+0], a[j4*4+1], a[j4*4+2], a[j4*4+3]);
    }
}

// ---------------------------------------------------------------------------
// K_conv: inline BN2 finalize (redundant per block, deterministic) +
// BN2+ELU + dw15 + pw(24->32). grid 1024 (64-t tiles), 256 thr.
// ---------------------------------------------------------------------------
__global__ void __launch_bounds__(256)
k_conv(const float* __restrict__ dwW,
       const float* __restrict__ pwW,
       const float* __restrict__ bn2_g,
       const float* __restrict__ bn2_b) {
    __shared__ float sh[24][80];         // 78 used (64 + 14 halo)
    __shared__ float sdw[24][16];
    __shared__ float spw[32][24];
    __shared__ float dwv[24][68];        // 64 used
    __shared__ float ssc2[24], ssh2[24];

    int b   = blockIdx.x >> 4;
    int t0  = (blockIdx.x & 15) * 64;
    int tid = threadIdx.x;
    int wid = tid >> 5, lane = tid & 31;

    for (int i = tid; i < 360; i += 256) sdw[i / 15][i % 15] = dwW[i];
    for (int i = tid; i < 768; i += 256) spw[i / 24][i % 24] = pwW[i];

    // BN2 finalize: warp wid handles channels wid*3..wid*3+2.
#pragma unroll
    for (int cc = 0; cc < 3; cc++) {
        int ch = wid * 3 + cc;
        const float* ps = g_ep_sum + ch * NCTA_ENC;
        const float* pq = g_ep_sq  + ch * NCTA_ENC;
        float s  = (ps[lane] + ps[lane + 32]) + (ps[lane + 64] + ps[lane + 96]);
        float qv = (pq[lane] + pq[lane + 32]) + (pq[lane + 64] + pq[lane + 96]);
#pragma unroll
        for (int off = 16; off > 0; off >>= 1) {
            s  += __shfl_xor_sync(0xffffffffu, s, off);
            qv += __shfl_xor_sync(0xffffffffu, qv, off);
        }
        if (lane == 0) {
            float mean = s * (1.0f / BT);
            float var  = fmaxf(qv * (1.0f / BT) - mean * mean, 0.0f);
            float sc   = __ldg(bn2_g + ch) * rsqrtf(var + 1e-5f);
            ssc2[ch] = sc;
            ssh2[ch] = __ldg(bn2_b + ch) - mean * sc;
        }
    }
    __syncthreads();

    for (int i = tid; i < 24 * 78; i += 256) {
        int ch = i / 78, j = i % 78;
        int t = t0 + j - 7;
        float v = 0.0f;
        if (t >= 0 && t < T) {
            float raw = g_s[(size_t)ch * BT + b * T + t];
            v = eluf(fmaf(raw, ssc2[ch], ssh2[ch]));
        }
        sh[ch][j] = v;
    }
    __syncthreads();

    {
        int tp = tid & 31;
        int cg = tid >> 5;
#pragma unroll
        for (int cc = 0; cc < 3; cc++) {
            int ch = cg * 3 + cc;
            float s[18];
#pragma unroll
            for (int j = 0; j < 9; j++) {
                float2 v = *(const float2*)&sh[ch][2 * tp + 2 * j];
                s[2*j] = v.x; s[2*j+1] = v.y;
            }
            float a0 = 0.0f, a1 = 0.0f;
#pragma unroll
            for (int k = 0; k < 15; k++) {
                float w = sdw[ch][k];
                a0 = fmaf(s[k],     w, a0);
                a1 = fmaf(s[k + 1], w, a1);
            }
            *(float2*)&dwv[ch][2 * tp] = make_float2(a0, a1);
        }
    }
    __syncthreads();

    int tl = tid & 63;
    int og = tid >> 6;
    float dreg[24];
#pragma unroll
    for (int ch = 0; ch < 24; ch++) dreg[ch] = dwv[ch][tl];

    int t = t0 + tl;
#pragma unroll
    for (int oo = 0; oo < 8; oo++) {
        int o = og * 8 + oo;
        float a = 0.0f;
#pragma unroll
        for (int c4 = 0; c4 < 6; c4++) {
            float4 w = *(const float4*)&spw[o][c4 * 4];
            a = fmaf(dreg[c4*4+0], w.x, a);
            a = fmaf(dreg[c4*4+1], w.y, a);
            a = fmaf(dreg[c4*4+2], w.z, a);
            a = fmaf(dreg[c4*4+3], w.w, a);
        }
        g_pw[(size_t)o * BT + b * T + t] = a;
    }
}

// ---------------------------------------------------------------------------
// K_pwstats: BN1 partials. Block = (ch, seg of 8192 floats). 256 blocks.
// ---------------------------------------------------------------------------
__global__ void __launch_bounds__(256)
k_pwstats() {
    int ch  = blockIdx.x >> 3;
    int seg = blockIdx.x & 7;
    const float4* p = (const float4*)(g_pw + (size_t)ch * BT + seg * 8192);

    float4 v[8];
#pragma unroll
    for (int j = 0; j < 8; j++) v[j] = p[threadIdx.x + 256 * j];

    float s = 0.0f, q = 0.0f;
#pragma unroll
    for (int j = 0; j < 8; j++) {
        s += v[j].x + v[j].y + v[j].z + v[j].w;
        q += v[j].x*v[j].x + v[j].y*v[j].y + v[j].z*v[j].z + v[j].w*v[j].w;
    }
    __shared__ float rs[8], rq[8];
    int w = threadIdx.x >> 5, lane = threadIdx.x & 31;
#pragma unroll
    for (int off = 16; off > 0; off >>= 1) {
        s += __shfl_xor_sync(0xffffffffu, s, off);
        q += __shfl_xor_sync(0xffffffffu, q, off);
    }
    if (lane == 0) { rs[w] = s; rq[w] = q; }
    __syncthreads();
    if (threadIdx.x == 0) {
        float S = 0.0f, Q = 0.0f;
#pragma unroll
        for (int ww = 0; ww < 8; ww++) { S += rs[ww]; Q += rq[ww]; }
        g_cp_sum[ch * 8 + seg] = S;
        g_cp_sq [ch * 8 + seg] = Q;
    }
}

// ---------------------------------------------------------------------------
// K_scan: bn1 finalize + prelif + PARALLEL cs/ts (8 chunk-warps, linear
// recurrence with tau^32 carry fixup) + light serial m-loop + FC.
// Dynamic smem: sx[256][33] + svth[256][33] + Lcs/Lts[8][32] + ssc/ssh.
// ---------------------------------------------------------------------------
__global__ void __launch_bounds__(256)
k_scan(const float* __restrict__ bn1_g,
       const float* __restrict__ bn1_b,
       const float* __restrict__ tau_geo,
       const float* __restrict__ beta_m,
       const float* __restrict__ alpha,
       const float* __restrict__ gamma_p,
       const float* __restrict__ fcW,
       const float* __restrict__ fcb,
       float* __restrict__ out) {
    extern __shared__ float dsm[];
    float (*sx)[33]   = (float(*)[33])dsm;              // 8448 floats
    float (*svth)[33] = (float(*)[33])(dsm + 8448);     // 8448
    float* Lcs = dsm + 16896;                           // 256
    float* Lts = Lcs + 256;                             // 256
    float* ssc = Lts + 256;                             // 32
    float* ssh = ssc + 32;                              // 32

    int b   = blockIdx.x;
    int tid = threadIdx.x;
    int w   = tid >> 5, lane = tid & 31;

    float tau    = 1.0f / (1.0f + expf(-tau_geo[0]));
    float om_tau = 1.0f - tau;

    // bn1 finalize
    {
        int ch = tid >> 3, p = tid & 7;
        float s = g_cp_sum[ch * 8 + p];
        float q = g_cp_sq [ch * 8 + p];
#pragma unroll
        for (int off = 4; off > 0; off >>= 1) {
            s += __shfl_xor_sync(0xffffffffu, s, off);
            q += __shfl_xor_sync(0xffffffffu, q, off);
        }
        if (p == 0) {
            float mean = s * (1.0f / BT);
            float var  = fmaxf(q * (1.0f / BT) - mean * mean, 0.0f);
            float sc   = bn1_g[ch] * rsqrtf(var + 1e-5f);
            ssc[ch] = sc;
            ssh[ch] = bn1_b[ch] - mean * sc;
        }
    }
    __syncthreads();

    // prelif: BN1+ELU+pool4 -> sx[tq][o]
    {
        int o = tid >> 3, p = tid & 7;
        const float4* src = (const float4*)(g_pw + (size_t)o * BT + b * T);
        float sc = ssc[o], shf = ssh[o];
#pragma unroll 4
        for (int k = 0; k < 32; k++) {
            int tq = p + 8 * k;
            float4 v = src[tq];
            float y0 = eluf(fmaf(v.x, sc, shf));
            float y1 = eluf(fmaf(v.y, sc, shf));
            float y2 = eluf(fmaf(v.z, sc, shf));
            float y3 = eluf(fmaf(v.w, sc, shf));
            sx[tq][o] = (y0 + y1 + y2 + y3) * 0.25f;
        }
    }

    // Pass 1: chunk-local cs/ts (zero init). warp w = chunk, lane = o.
    const float* cup = g_curv + (size_t)b * (TQ * 32) + lane;
    const float* tap = g_tang + (size_t)b * (TQ * 32) + lane;
    {
        float cs = 0.0f, ts = 0.0f;
#pragma unroll
        for (int bk = 0; bk < 4; bk++) {
            float cu8[8], ta8[8];
#pragma unroll
            for (int j = 0; j < 8; j++) {
                int t = w * 32 + bk * 8 + j;
                cu8[j] = cup[t * 32];
                ta8[j] = tap[t * 32];
            }
#pragma unroll
            for (int j = 0; j < 8; j++) {
                cs = fmaf(tau, cs, om_tau * cu8[j]);
                ts = fmaf(tau, ts, om_tau * ta8[j]);
            }
        }
        Lcs[w * 32 + lane] = cs;
        Lts[w * 32 + lane] = ts;
    }
    __syncthreads();

    // Pass 2: true init via Horner over previous chunks, then recompute,
    // emitting vth -> svth and xs = x*sens -> sx.
    {
        float f32 = tau;                         // tau^32 by squaring
        f32 = f32 * f32;   // ^2
        f32 = f32 * f32;   // ^4
        f32 = f32 * f32;   // ^8
        f32 = f32 * f32;   // ^16
        f32 = f32 * f32;   // ^32

        float Ics = 0.0f, Its = 0.0f;
        for (int j = 0; j < w; j++) {
            Ics = fmaf(Ics, f32, Lcs[j * 32 + lane]);
            Its = fmaf(Its, f32, Lts[j * 32 + lane]);
        }

        float al = alpha[0];
        float gp = gamma_p[0];
        float cs = Ics, ts = Its;
#pragma unroll
        for (int bk = 0; bk < 4; bk++) {
            float cu8[8], ta8[8];
#pragma unroll
            for (int j = 0; j < 8; j++) {
                int t = w * 32 + bk * 8 + j;
                cu8[j] = cup[t * 32];
                ta8[j] = tap[t * 32];
            }
#pragma unroll
            for (int j = 0; j < 8; j++) {
                int t = w * 32 + bk * 8 + j;
                cs = fmaf(tau, cs, om_tau * cu8[j]);
                ts = fmaf(tau, ts, om_tau * ta8[j]);
                svth[t][lane] = fmaxf(fmaf(al, cs, 0.3f), 0.1f);
                float a    = fmaf(-gp, ts, 1.0f);
                float sens = 1.0f / (1.0f + expf(-a));
                sx[t][lane] *= sens;
            }
        }
    }
    __syncthreads();

    // Serial m-loop (warp 0) + FC.
    if (tid < 32) {
        int o = tid;
        float beta = beta_m[0];
        float m = 0.0f, fr = 0.0f;
#pragma unroll 8
        for (int t = 0; t < TQ; t++) {
            float mn  = fmaf(beta, m, sx[t][o]);
            float dif = mn - svth[t][o];
            bool  sp  = dif > 0.0f;
            m = sp ? dif : mn;
            fr += sp ? 1.0f : 0.0f;
        }
        fr *= (1.0f / (float)TQ);

        float res[4];
#pragma unroll
        for (int k = 0; k < 4; k++) {
            float vv = fr * __ldg(fcW + k * 32 + o);
#pragma unroll
            for (int off = 16; off > 0; off >>= 1)
                vv += __shfl_xor_sync(0xffffffffu, vv, off);
            res[k] = vv;
        }
        if (o == 0) {
#pragma unroll
            for (int k = 0; k < 4; k++)
                out[b * 4 + k] = res[k] + __ldg(fcb + k);
        }
    }
}

// ---------------------------------------------------------------------------
extern "C" void kernel_launch(void* const* d_in, const int* in_sizes, int n_in,
                              void* d_out, int out_size) {
    const float* xb       = (const float*)d_in[0];
    const float* mu       = (const float*)d_in[1];
    const float* sigma    = (const float*)d_in[2];
    const float* curvW    = (const float*)d_in[3];
    const float* tangW    = (const float*)d_in[4];
    const float* spatialW = (const float*)d_in[5];
    const float* bn2_g    = (const float*)d_in[6];
    const float* bn2_b    = (const float*)d_in[7];
    const float* dwW      = (const float*)d_in[8];
    const float* pwW      = (const float*)d_in[9];
    const float* bn1_g    = (const float*)d_in[10];
    const float* bn1_b    = (const float*)d_in[11];
    const float* tau_geo  = (const float*)d_in[12];
    const float* beta_m   = (const float*)d_in[13];
    const float* alpha    = (const float*)d_in[14];
    const float* gamma_p  = (const float*)d_in[15];
    const float* fcW      = (const float*)d_in[16];
    const float* fcb      = (const float*)d_in[17];
    float* out            = (float*)d_out;

    static bool attr_set = false;
    const int scan_smem = (8448 * 2 + 512 + 64) * 4;   // 69888 B
    if (!attr_set) {
        cudaFuncSetAttribute(k_scan, cudaFuncAttributeMaxDynamicSharedMemorySize,
                             scan_smem);
        attr_set = true;
    }

    k_front<<<640, 256>>>(xb, curvW, tangW, mu, sigma, spatialW);
    k_conv<<<1024, 256>>>(dwW, pwW, bn2_g, bn2_b);
    k_pwstats<<<256, 256>>>();
    k_scan<<<64, 256, scan_smem>>>(bn1_g, bn1_b, tau_geo, beta_m, alpha,
                                   gamma_p, fcW, fcb, out);
}